// round 13
// baseline (speedup 1.0000x reference)
#include <cuda_runtime.h>
#include <cuda_fp16.h>
#include <math.h>
#include <stdint.h>

// Problem dims (fixed)
#define BDIM   128
#define NDIM   512
#define DDIM   512
#define MROWS  (BDIM*NDIM)          // 65536
#define H1DIM  512
#define H2DIM  256
#define H3DIM  128

// ---------------- static scratch ----------------
__device__ __half g_ia[(size_t)MROWS * DDIM];
__device__ __half g_h1[(size_t)MROWS * H1DIM];
__device__ __half g_wL[H1DIM * DDIM];
__device__ __half g_w1[H2DIM * H1DIM];
__device__ __half g_w2[H3DIM * H2DIM];
__device__ float  g_cm[MROWS];
__device__ float  g_mk[MROWS];
__device__ int    g_count;
__device__ int    g_list[MROWS];

// ---------------- helpers ----------------
__device__ __forceinline__ float gelu_exact(float x) {
    return 0.5f * x * (1.0f + erff(x * 0.70710678118654752f));
}
__device__ __forceinline__ uint32_t smem_u32(const void* p) {
    uint32_t a;
    asm("{ .reg .u64 t; cvta.to.shared.u64 t, %1; cvt.u32.u64 %0, t; }" : "=r"(a) : "l"(p));
    return a;
}
__device__ __forceinline__ void cp16(uint32_t s, const void* g) {
    asm volatile("cp.async.cg.shared.global [%0], [%1], 16;" :: "r"(s), "l"(g));
}
__device__ __forceinline__ void ldsm_x4(uint32_t addr, uint32_t& r0, uint32_t& r1,
                                        uint32_t& r2, uint32_t& r3) {
    asm volatile("ldmatrix.sync.aligned.m8n8.x4.shared.b16 {%0,%1,%2,%3}, [%4];"
                 : "=r"(r0), "=r"(r1), "=r"(r2), "=r"(r3) : "r"(addr));
}
__device__ __forceinline__ void mma16816(float* c, const uint32_t* a, const uint32_t* b) {
    asm volatile("mma.sync.aligned.m16n8k16.row.col.f32.f16.f16.f32 "
                 "{%0,%1,%2,%3}, {%4,%5,%6,%7}, {%8,%9}, {%0,%1,%2,%3};"
                 : "+f"(c[0]), "+f"(c[1]), "+f"(c[2]), "+f"(c[3])
                 : "r"(a[0]), "r"(a[1]), "r"(a[2]), "r"(a[3]), "r"(b[0]), "r"(b[1]));
}

// ---------------- conv: input f2h + 3 weight f2h + counter reset, ONE launch ----------------
__global__ void conv_kernel(const float* __restrict__ x,
                            const float* __restrict__ wL, const float* __restrict__ w1,
                            const float* __restrict__ w2) {
    const int nIn = MROWS * DDIM / 4;
    const int n1 = H1DIM * DDIM / 4, n2 = H2DIM * H1DIM / 4, n3 = H3DIM * H2DIM / 4;
    int i = blockIdx.x * blockDim.x + threadIdx.x;
    if (i == 0) g_count = 0;
    const float* src; __half* dst; int j;
    if (i < nIn)                      { src = x;  dst = g_ia; j = i; }
    else if ((j = i - nIn) < n1)      { src = wL; dst = g_wL; }
    else if ((j -= n1) < n2)          { src = w1; dst = g_w1; }
    else if ((j -= n2) < n3)          { src = w2; dst = g_w2; }
    else return;
    float4 v = ((const float4*)src)[j];
    ((__half2*)dst)[2 * j + 0] = __floats2half2_rn(v.x, v.y);
    ((__half2*)dst)[2 * j + 1] = __floats2half2_rn(v.z, v.w);
}

// ---------------- layer-1 GEMM (128x128 tile, BK=64, 2-stage, 2 CTA/SM) ----------------
#define BK 64
#define RSTR 72                                    // halfs per smem row (144 B)
#define OP_B    (128 * RSTR * 2)                   // 18432 B
#define STAGE_B (2 * OP_B)                         // 36864 B
#define GEMM_SMEM (2 * STAGE_B)                    // 73728 B

__global__ __launch_bounds__(256, 2)
void hgemm_l1(const __half* __restrict__ A, const __half* __restrict__ B,
              __half* __restrict__ C, int K, int N) {
    extern __shared__ __align__(16) char smem[];

    const int tid  = threadIdx.x;
    const int lane = tid & 31;
    const int wid  = tid >> 5;
    const int warpM = wid & 3;
    const int warpN = wid >> 2;
    const int bm = blockIdx.y * 128;
    const int bn = blockIdx.x * 128;

    float acc[2][8][4];
#pragma unroll
    for (int f = 0; f < 2; ++f)
#pragma unroll
        for (int n = 0; n < 8; ++n)
#pragma unroll
            for (int q = 0; q < 4; ++q) acc[f][n][q] = 0.0f;

    const int nc = K / BK;

    auto load_tiles = [&](int c, int buf) {
        const __half* ag = A + (size_t)bm * K + c * BK;
        const __half* bg = B + (size_t)bn * K + c * BK;
        uint32_t sa = smem_u32(smem + buf * STAGE_B);
        uint32_t sb = sa + OP_B;
#pragma unroll
        for (int it = 0; it < 4; ++it) {
            int t = it * 256 + tid;
            int row = t >> 3, q = t & 7;
            cp16(sa + row * (RSTR * 2) + q * 16, ag + (size_t)row * K + q * 8);
        }
#pragma unroll
        for (int it = 0; it < 4; ++it) {
            int t = it * 256 + tid;
            int row = t >> 3, q = t & 7;
            cp16(sb + row * (RSTR * 2) + q * 16, bg + (size_t)row * K + q * 8);
        }
        asm volatile("cp.async.commit_group;");
    };

    load_tiles(0, 0);

    for (int c = 0; c < nc; ++c) {
        if (c + 1 < nc) {
            load_tiles(c + 1, (c + 1) & 1);
            asm volatile("cp.async.wait_group 1;");
        } else {
            asm volatile("cp.async.wait_group 0;");
        }
        __syncthreads();

        const int buf = c & 1;
        uint32_t aBase = smem_u32(smem + buf * STAGE_B);
        uint32_t bBase = aBase + OP_B;
        const int mat = lane >> 3, r8 = lane & 7;

#pragma unroll
        for (int ks = 0; ks < 4; ++ks) {
            uint32_t a[2][4];
#pragma unroll
            for (int f = 0; f < 2; ++f) {
                int row = warpM * 32 + f * 16 + (mat & 1) * 8 + r8;
                int kh  = mat >> 1;
                ldsm_x4(aBase + row * (RSTR * 2) + ks * 32 + kh * 16,
                        a[f][0], a[f][1], a[f][2], a[f][3]);
            }
            uint32_t b[8][2];
#pragma unroll
            for (int p = 0; p < 4; ++p) {
                int row = warpN * 64 + p * 16 + (mat >> 1) * 8 + r8;
                int kh  = mat & 1;
                uint32_t r0, r1, r2, r3;
                ldsm_x4(bBase + row * (RSTR * 2) + ks * 32 + kh * 16, r0, r1, r2, r3);
                b[2 * p][0] = r0; b[2 * p][1] = r1;
                b[2 * p + 1][0] = r2; b[2 * p + 1][1] = r3;
            }
#pragma unroll
            for (int f = 0; f < 2; ++f)
#pragma unroll
                for (int n = 0; n < 8; ++n)
                    mma16816(acc[f][n], a[f], b[n]);
        }
        __syncthreads();
    }

#pragma unroll
    for (int f = 0; f < 2; ++f) {
        int m0 = bm + warpM * 32 + f * 16 + (lane >> 2);
#pragma unroll
        for (int n = 0; n < 8; ++n) {
            int col = bn + warpN * 64 + n * 8 + 2 * (lane & 3);
            __half2 v0 = __floats2half2_rn(gelu_exact(acc[f][n][0]), gelu_exact(acc[f][n][1]));
            __half2 v1 = __floats2half2_rn(gelu_exact(acc[f][n][2]), gelu_exact(acc[f][n][3]));
            *(__half2*)(C + (size_t)m0 * N + col)       = v0;
            *(__half2*)(C + (size_t)(m0 + 8) * N + col) = v1;
        }
    }
}

// ---------------- fused layers 2+3: h1 -> h2(smem) -> z -> decision ----------------
#define OPA23 (128 * RSTR * 2)                     // 18432
#define OPB23 (256 * RSTR * 2)                     // 36864
#define STAGE23 (OPA23 + OPB23)                    // 55296
#define HS_STRIDE 264                              // halfs per row (528 B)
#define HS_BYTES (128 * HS_STRIDE * 2)             // 67584
#define F23_SMEM (3 * STAGE23 + 4 * 128 * 4)       // 167936

__global__ __launch_bounds__(512, 1)
void fused23(const __half* __restrict__ A,         // h1 [M,512]
             const __half* __restrict__ Bw1,       // w1 [256,512]
             const __half* __restrict__ Bw2,       // w2 [128,256]
             const float* __restrict__ w3, const float* __restrict__ prev_m) {
    extern __shared__ __align__(16) char smem[];

    const int tid  = threadIdx.x;
    const int lane = tid & 31;
    const int wid  = tid >> 5;
    const int warpM = wid & 3;
    const int warpN = wid >> 2;
    const int bm = blockIdx.x * 128;
    const int K = H1DIM;

    float acc[2][8][4];
#pragma unroll
    for (int f = 0; f < 2; ++f)
#pragma unroll
        for (int n = 0; n < 8; ++n)
#pragma unroll
            for (int q = 0; q < 4; ++q) acc[f][n][q] = 0.0f;

    const int nc = K / BK;            // 8

    auto load_tiles = [&](int c, int buf) {
        const __half* ag = A + (size_t)bm * K + c * BK;
        const __half* bg = Bw1 + c * BK;
        uint32_t sa = smem_u32(smem + buf * STAGE23);
        uint32_t sb = sa + OPA23;
#pragma unroll
        for (int it = 0; it < 2; ++it) {
            int t = it * 512 + tid;
            int row = t >> 3, q = t & 7;
            cp16(sa + row * (RSTR * 2) + q * 16, ag + (size_t)row * K + q * 8);
        }
#pragma unroll
        for (int it = 0; it < 4; ++it) {
            int t = it * 512 + tid;
            int row = t >> 3, q = t & 7;
            cp16(sb + row * (RSTR * 2) + q * 16, bg + (size_t)row * K + q * 8);
        }
        asm volatile("cp.async.commit_group;");
    };

    load_tiles(0, 0);
    load_tiles(1, 1);

    for (int c = 0; c < nc; ++c) {
        if (c + 1 < nc) {
            asm volatile("cp.async.wait_group 1;");
        } else {
            asm volatile("cp.async.wait_group 0;");
        }
        __syncthreads();
        if (c + 2 < nc) load_tiles(c + 2, (c + 2) % 3);

        const int buf = c % 3;
        uint32_t aBase = smem_u32(smem + buf * STAGE23);
        uint32_t bBase = aBase + OPA23;
        const int mat = lane >> 3, r8 = lane & 7;

#pragma unroll
        for (int ks = 0; ks < 4; ++ks) {
            uint32_t a[2][4];
#pragma unroll
            for (int f = 0; f < 2; ++f) {
                int row = warpM * 32 + f * 16 + (mat & 1) * 8 + r8;
                int kh  = mat >> 1;
                ldsm_x4(aBase + row * (RSTR * 2) + ks * 32 + kh * 16,
                        a[f][0], a[f][1], a[f][2], a[f][3]);
            }
            uint32_t b[8][2];
#pragma unroll
            for (int p = 0; p < 4; ++p) {
                int row = warpN * 64 + p * 16 + (mat >> 1) * 8 + r8;
                int kh  = mat & 1;
                uint32_t r0, r1, r2, r3;
                ldsm_x4(bBase + row * (RSTR * 2) + ks * 32 + kh * 16, r0, r1, r2, r3);
                b[2 * p][0] = r0; b[2 * p][1] = r1;
                b[2 * p + 1][0] = r2; b[2 * p + 1][1] = r3;
            }
#pragma unroll
            for (int f = 0; f < 2; ++f)
#pragma unroll
                for (int n = 0; n < 8; ++n)
                    mma16816(acc[f][n], a[f], b[n]);
        }
    }
    __syncthreads();

    // ---- handoff: h2 = gelu(acc) -> smem (fp16); w2 -> smem via cp.async ----
    __half* hs = (__half*)smem;
    uint32_t w2s = smem_u32(smem + HS_BYTES);
#pragma unroll
    for (int it = 0; it < 8; ++it) {
        int t = it * 512 + tid;
        int row = t >> 5, q = t & 31;
        cp16(w2s + row * (HS_STRIDE * 2) + q * 16, Bw2 + (size_t)row * H2DIM + q * 8);
    }
    asm volatile("cp.async.commit_group;");

#pragma unroll
    for (int f = 0; f < 2; ++f) {
        int m0 = warpM * 32 + f * 16 + (lane >> 2);
#pragma unroll
        for (int n = 0; n < 8; ++n) {
            int col = warpN * 64 + n * 8 + 2 * (lane & 3);
            __half2 v0 = __floats2half2_rn(gelu_exact(acc[f][n][0]), gelu_exact(acc[f][n][1]));
            __half2 v1 = __floats2half2_rn(gelu_exact(acc[f][n][2]), gelu_exact(acc[f][n][3]));
            *(__half2*)(hs + (size_t)m0 * HS_STRIDE + col)       = v0;
            *(__half2*)(hs + (size_t)(m0 + 8) * HS_STRIDE + col) = v1;
        }
    }
    asm volatile("cp.async.wait_group 0;");
    __syncthreads();

    // ---- phase 2: y3[128,128] = h2[128,256] * w2[128,256]^T ----
    float acc2[2][4][4];
#pragma unroll
    for (int f = 0; f < 2; ++f)
#pragma unroll
        for (int n = 0; n < 4; ++n)
#pragma unroll
            for (int q = 0; q < 4; ++q) acc2[f][n][q] = 0.0f;

    {
        uint32_t aBase = smem_u32(hs);
        uint32_t bBase = w2s;
        const int mat = lane >> 3, r8 = lane & 7;
#pragma unroll
        for (int k16 = 0; k16 < 16; ++k16) {
            uint32_t a[2][4];
#pragma unroll
            for (int f = 0; f < 2; ++f) {
                int row = warpM * 32 + f * 16 + (mat & 1) * 8 + r8;
                int kh  = mat >> 1;
                ldsm_x4(aBase + row * (HS_STRIDE * 2) + k16 * 32 + kh * 16,
                        a[f][0], a[f][1], a[f][2], a[f][3]);
            }
            uint32_t b[4][2];
#pragma unroll
            for (int p = 0; p < 2; ++p) {
                int row = warpN * 32 + p * 16 + (mat >> 1) * 8 + r8;
                int kh  = mat & 1;
                uint32_t r0, r1, r2, r3;
                ldsm_x4(bBase + row * (HS_STRIDE * 2) + k16 * 32 + kh * 16, r0, r1, r2, r3);
                b[2 * p][0] = r0; b[2 * p][1] = r1;
                b[2 * p + 1][0] = r2; b[2 * p + 1][1] = r3;
            }
#pragma unroll
            for (int f = 0; f < 2; ++f)
#pragma unroll
                for (int n = 0; n < 4; ++n)
                    mma16816(acc2[f][n], a[f], b[n]);
        }
    }

    // ---- logit epilogue ----
    float* zsm = (float*)(smem + 3 * STAGE23);
    float zp[2][2];
    zp[0][0] = zp[0][1] = zp[1][0] = zp[1][1] = 0.0f;
#pragma unroll
    for (int f = 0; f < 2; ++f) {
#pragma unroll
        for (int n = 0; n < 4; ++n) {
            int col = warpN * 32 + n * 8 + 2 * (lane & 3);
            float w0 = __ldg(w3 + col), w1v = __ldg(w3 + col + 1);
            zp[f][0] += gelu_exact(acc2[f][n][0]) * w0 + gelu_exact(acc2[f][n][1]) * w1v;
            zp[f][1] += gelu_exact(acc2[f][n][2]) * w0 + gelu_exact(acc2[f][n][3]) * w1v;
        }
    }
#pragma unroll
    for (int f = 0; f < 2; ++f)
#pragma unroll
        for (int h = 0; h < 2; ++h) {
            float s = zp[f][h];
            s += __shfl_xor_sync(0xFFFFFFFFu, s, 1);
            s += __shfl_xor_sync(0xFFFFFFFFu, s, 2);
            zp[f][h] = s;
        }
    if ((lane & 3) == 0) {
#pragma unroll
        for (int f = 0; f < 2; ++f)
#pragma unroll
            for (int h = 0; h < 2; ++h)
                zsm[warpN * 128 + warpM * 32 + f * 16 + (lane >> 2) + 8 * h] = zp[f][h];
    }
    __syncthreads();
    if (tid < 128) {
        float s = zsm[tid] + zsm[128 + tid] + zsm[256 + tid] + zsm[384 + tid];
        int row = bm + tid;
        float pm = prev_m[row];
        float prob = 1.0f / (1.0f + expf(-s));
        float cm_raw = prob * pm;
        bool hard = cm_raw > 0.5f;
        g_cm[row] = hard ? 1.0f : 1e-10f;
        g_mk[row] = hard ? 1.0f : 0.0f;
        float thr = 5e-4f * fmaxf(1.0f, fabsf(pm));
        if (fabsf(cm_raw - 0.5f) < thr) {
            int idx = atomicAdd(&g_count, 1);
            g_list[idx] = row;
        }
    }
}

// ---------------- exact fp32 recompute: 512 threads, prefetched weights ----------------
#define RG 16
#define RC_SMEM (RG * 512 * 2 * 4)   // 65536 B
__global__ __launch_bounds__(512)
void recompute_kernel(const float* __restrict__ x, const float* __restrict__ W_L,
                      const float* __restrict__ W_l1, const float* __restrict__ W_l2,
                      const float* __restrict__ w3, const float* __restrict__ prev_m) {
    extern __shared__ float sm[];
    float* xs  = sm;            // [RG][512]
    float* h1s = sm + RG * 512; // [RG][512]
    float* h2s = sm;            // [RG][256] overwrites xs after layer1
    float* h3s = sm + RG * 256; // [RG][128]

    const int tid = threadIdx.x;
    const int count = g_count;

    for (int base = blockIdx.x * RG; base < count; base += gridDim.x * RG) {
        const int nr = min(RG, count - base);

        for (int e = tid; e < RG * 512; e += 512) {
            int r = e >> 9, k = e & 511;
            xs[e] = (r < nr) ? x[(size_t)g_list[base + r] * DDIM + k] : 0.0f;
        }
        __syncthreads();

        // ---- layer1: 1 output/thread (j=tid), 16 rows, 4-deep weight prefetch ----
        {
            const int j = tid;
            float a[RG];
#pragma unroll
            for (int r = 0; r < RG; ++r) a[r] = 0.0f;
            const float4* wr = (const float4*)(W_L + (size_t)j * DDIM);
            for (int k4 = 0; k4 < 128; k4 += 4) {
                float4 w[4];
#pragma unroll
                for (int u = 0; u < 4; ++u) w[u] = wr[k4 + u];
#pragma unroll
                for (int u = 0; u < 4; ++u)
#pragma unroll
                    for (int r = 0; r < RG; ++r) {
                        const float* xr = xs + r * 512 + (k4 + u) * 4;
                        a[r] = fmaf(xr[0], w[u].x, a[r]);
                        a[r] = fmaf(xr[1], w[u].y, a[r]);
                        a[r] = fmaf(xr[2], w[u].z, a[r]);
                        a[r] = fmaf(xr[3], w[u].w, a[r]);
                    }
            }
#pragma unroll
            for (int r = 0; r < RG; ++r) h1s[r * 512 + j] = gelu_exact(a[r]);
        }
        __syncthreads();

        // ---- layer2: j=tid&255, row-half tid>>8; 8 rows each ----
        {
            const int j = tid & 255;
            const int r0 = (tid >> 8) * 8;
            float a[8];
#pragma unroll
            for (int r = 0; r < 8; ++r) a[r] = 0.0f;
            const float4* wr = (const float4*)(W_l1 + (size_t)j * H1DIM);
            for (int k4 = 0; k4 < 128; k4 += 4) {
                float4 w[4];
#pragma unroll
                for (int u = 0; u < 4; ++u) w[u] = wr[k4 + u];
#pragma unroll
                for (int u = 0; u < 4; ++u)
#pragma unroll
                    for (int r = 0; r < 8; ++r) {
                        const float* hr = h1s + (r0 + r) * 512 + (k4 + u) * 4;
                        a[r] = fmaf(hr[0], w[u].x, a[r]);
                        a[r] = fmaf(hr[1], w[u].y, a[r]);
                        a[r] = fmaf(hr[2], w[u].z, a[r]);
                        a[r] = fmaf(hr[3], w[u].w, a[r]);
                    }
            }
            // h2s aliases xs (dead since the post-layer1 barrier); h1s untouched
#pragma unroll
            for (int r = 0; r < 8; ++r) h2s[(r0 + r) * 256 + j] = gelu_exact(a[r]);
        }
        __syncthreads();

        // ---- layer3: j=tid&127, row-quarter tid>>7; 4 rows each ----
        {
            const int j = tid & 127;
            const int r0 = (tid >> 7) * 4;
            float a[4];
#pragma unroll
            for (int r = 0; r < 4; ++r) a[r] = 0.0f;
            const float4* wr = (const float4*)(W_l2 + (size_t)j * H2DIM);
            for (int k4 = 0; k4 < 64; k4 += 4) {
                float4 w[4];
#pragma unroll
                for (int u = 0; u < 4; ++u) w[u] = wr[k4 + u];
#pragma unroll
                for (int u = 0; u < 4; ++u)
#pragma unroll
                    for (int r = 0; r < 4; ++r) {
                        const float* hr = h2s + (r0 + r) * 256 + (k4 + u) * 4;
                        a[r] = fmaf(hr[0], w[u].x, a[r]);
                        a[r] = fmaf(hr[1], w[u].y, a[r]);
                        a[r] = fmaf(hr[2], w[u].z, a[r]);
                        a[r] = fmaf(hr[3], w[u].w, a[r]);
                    }
            }
#pragma unroll
            for (int r = 0; r < 4; ++r) h3s[(r0 + r) * 128 + j] = gelu_exact(a[r]);
        }
        __syncthreads();

        // ---- z + decision: 16 warps, warp w handles row w ----
        {
            const int warp = tid >> 5, lane = tid & 31;
            const int r = warp;
            float4 a4 = ((const float4*)(h3s + r * 128))[lane];
            float4 w4 = ((const float4*)w3)[lane];
            float s = a4.x * w4.x + a4.y * w4.y + a4.z * w4.z + a4.w * w4.w;
#pragma unroll
            for (int off = 16; off > 0; off >>= 1)
                s += __shfl_xor_sync(0xFFFFFFFFu, s, off);
            if (lane == 0 && r < nr) {
                int row = g_list[base + r];
                float pm = prev_m[row];
                float prob = 1.0f / (1.0f + expf(-s));
                bool hard = prob * pm > 0.5f;
                g_cm[row] = hard ? 1.0f : 1e-10f;
                g_mk[row] = hard ? 1.0f : 0.0f;
            }
        }
        __syncthreads();
    }
}

// ---------------- finalize: scale input by cm, emit mask/cm ----------------
__global__ __launch_bounds__(256)
void finalize_kernel(const float* __restrict__ x, float* __restrict__ out,
                     float* __restrict__ mask_out, float* __restrict__ cm_out) {
    const int warp = threadIdx.x >> 5;
    const int lane = threadIdx.x & 31;
    const size_t row = (size_t)blockIdx.x * 8 + warp;

    float cm = g_cm[row];
    if (lane == 0) {
        mask_out[row] = g_mk[row];
        cm_out[row]   = cm;
    }
    const float4* xin = (const float4*)(x + row * DDIM);
    float4*       xo  = (float4*)(out + row * DDIM);
#pragma unroll
    for (int i = 0; i < 4; ++i) {
        float4 v = xin[lane + 32 * i];
        v.x *= cm; v.y *= cm; v.z *= cm; v.w *= cm;
        __stcs(xo + lane + 32 * i, v);
    }
}

// ---------------- launch ----------------
extern "C" void kernel_launch(void* const* d_in, const int* in_sizes, int n_in,
                              void* d_out, int out_size) {
    const float* input  = (const float*)d_in[0];
    const float* prev_m = (const float*)d_in[2];
    const float* W_L    = (const float*)d_in[3];
    const float* W_l1   = (const float*)d_in[4];
    const float* W_l2   = (const float*)d_in[5];
    const float* W_l3   = (const float*)d_in[6];

    float* out      = (float*)d_out;
    float* mask_out = out + (size_t)MROWS * DDIM;
    float* cm_out   = mask_out + MROWS;

    __half *ia, *h1, *wL, *w1, *w2;
    cudaGetSymbolAddress((void**)&ia, g_ia);
    cudaGetSymbolAddress((void**)&h1, g_h1);
    cudaGetSymbolAddress((void**)&wL, g_wL);
    cudaGetSymbolAddress((void**)&w1, g_w1);
    cudaGetSymbolAddress((void**)&w2, g_w2);

    cudaFuncSetAttribute(hgemm_l1, cudaFuncAttributeMaxDynamicSharedMemorySize, GEMM_SMEM);
    cudaFuncSetAttribute(fused23,  cudaFuncAttributeMaxDynamicSharedMemorySize, F23_SMEM);
    cudaFuncSetAttribute(recompute_kernel, cudaFuncAttributeMaxDynamicSharedMemorySize, RC_SMEM);

    // 1: all conversions + counter reset (single launch)
    {
        int ntot = MROWS * DDIM / 4 + (H1DIM * DDIM + H2DIM * H1DIM + H3DIM * H2DIM) / 4;
        conv_kernel<<<(ntot + 255) / 256, 256>>>(input, W_L, W_l1, W_l2);
    }

    // 2: layer 1 GEMM
    hgemm_l1<<<dim3(H1DIM / 128, MROWS / 128), 256, GEMM_SMEM>>>(ia, wL, h1, DDIM, H1DIM);

    // 3: fused layers 2+3 + logit + decision
    fused23<<<MROWS / 128, 512, F23_SMEM>>>(h1, w1, w2, W_l3, prev_m);

    // 4-5: exact recompute of ambiguous rows (512 thr, prefetched), then output
    recompute_kernel<<<256, 512, RC_SMEM>>>(input, W_L, W_l1, W_l2, W_l3, prev_m);
    finalize_kernel<<<MROWS / 8, 256>>>(input, out, mask_out, cm_out);
}

// round 14
// speedup vs baseline: 1.4791x; 1.4791x over previous
#include <cuda_runtime.h>
#include <cuda_fp16.h>
#include <math.h>
#include <stdint.h>

// Problem dims (fixed)
#define BDIM   128
#define NDIM   512
#define DDIM   512
#define MROWS  (BDIM*NDIM)          // 65536
#define H1DIM  512
#define H2DIM  256
#define H3DIM  128

// ---------------- static scratch ----------------
__device__ __half g_ia[(size_t)MROWS * DDIM];
__device__ __half g_h1[(size_t)MROWS * H1DIM];
__device__ __half g_wL[H1DIM * DDIM];
__device__ __half g_w1[H2DIM * H1DIM];
__device__ __half g_w2[H3DIM * H2DIM];
__device__ float  g_cm[MROWS];
__device__ float  g_mk[MROWS];
__device__ unsigned char g_flag[MROWS];
__device__ int    g_count;
__device__ int    g_list[MROWS];

// ---------------- helpers ----------------
__device__ __forceinline__ float gelu_exact(float x) {
    return 0.5f * x * (1.0f + erff(x * 0.70710678118654752f));
}
__device__ __forceinline__ uint32_t smem_u32(const void* p) {
    uint32_t a;
    asm("{ .reg .u64 t; cvta.to.shared.u64 t, %1; cvt.u32.u64 %0, t; }" : "=r"(a) : "l"(p));
    return a;
}
__device__ __forceinline__ void cp16(uint32_t s, const void* g) {
    asm volatile("cp.async.cg.shared.global [%0], [%1], 16;" :: "r"(s), "l"(g));
}
__device__ __forceinline__ void ldsm_x4(uint32_t addr, uint32_t& r0, uint32_t& r1,
                                        uint32_t& r2, uint32_t& r3) {
    asm volatile("ldmatrix.sync.aligned.m8n8.x4.shared.b16 {%0,%1,%2,%3}, [%4];"
                 : "=r"(r0), "=r"(r1), "=r"(r2), "=r"(r3) : "r"(addr));
}
__device__ __forceinline__ void mma16816(float* c, const uint32_t* a, const uint32_t* b) {
    asm volatile("mma.sync.aligned.m16n8k16.row.col.f32.f16.f16.f32 "
                 "{%0,%1,%2,%3}, {%4,%5,%6,%7}, {%8,%9}, {%0,%1,%2,%3};"
                 : "+f"(c[0]), "+f"(c[1]), "+f"(c[2]), "+f"(c[3])
                 : "r"(a[0]), "r"(a[1]), "r"(a[2]), "r"(a[3]), "r"(b[0]), "r"(b[1]));
}

// ---------------- conv: input f2h + 3 weight f2h + counter reset, ONE launch ----------------
__global__ void conv_kernel(const float* __restrict__ x,
                            const float* __restrict__ wL, const float* __restrict__ w1,
                            const float* __restrict__ w2) {
    const int nIn = MROWS * DDIM / 4;
    const int n1 = H1DIM * DDIM / 4, n2 = H2DIM * H1DIM / 4, n3 = H3DIM * H2DIM / 4;
    int i = blockIdx.x * blockDim.x + threadIdx.x;
    if (i == 0) g_count = 0;
    const float* src; __half* dst; int j;
    if (i < nIn)                      { src = x;  dst = g_ia; j = i; }
    else if ((j = i - nIn) < n1)      { src = wL; dst = g_wL; }
    else if ((j -= n1) < n2)          { src = w1; dst = g_w1; }
    else if ((j -= n2) < n3)          { src = w2; dst = g_w2; }
    else return;
    float4 v = ((const float4*)src)[j];
    ((__half2*)dst)[2 * j + 0] = __floats2half2_rn(v.x, v.y);
    ((__half2*)dst)[2 * j + 1] = __floats2half2_rn(v.z, v.w);
}

// ---------------- layer-1 GEMM (128x128 tile, BK=64, 2-stage, 2 CTA/SM) ----------------
#define BK 64
#define RSTR 72                                    // halfs per smem row (144 B)
#define OP_B    (128 * RSTR * 2)                   // 18432 B
#define STAGE_B (2 * OP_B)                         // 36864 B
#define GEMM_SMEM (2 * STAGE_B)                    // 73728 B

__global__ __launch_bounds__(256, 2)
void hgemm_l1(const __half* __restrict__ A, const __half* __restrict__ B,
              __half* __restrict__ C, int K, int N) {
    extern __shared__ __align__(16) char smem[];

    const int tid  = threadIdx.x;
    const int lane = tid & 31;
    const int wid  = tid >> 5;
    const int warpM = wid & 3;
    const int warpN = wid >> 2;
    const int bm = blockIdx.y * 128;
    const int bn = blockIdx.x * 128;

    float acc[2][8][4];
#pragma unroll
    for (int f = 0; f < 2; ++f)
#pragma unroll
        for (int n = 0; n < 8; ++n)
#pragma unroll
            for (int q = 0; q < 4; ++q) acc[f][n][q] = 0.0f;

    const int nc = K / BK;

    auto load_tiles = [&](int c, int buf) {
        const __half* ag = A + (size_t)bm * K + c * BK;
        const __half* bg = B + (size_t)bn * K + c * BK;
        uint32_t sa = smem_u32(smem + buf * STAGE_B);
        uint32_t sb = sa + OP_B;
#pragma unroll
        for (int it = 0; it < 4; ++it) {
            int t = it * 256 + tid;
            int row = t >> 3, q = t & 7;
            cp16(sa + row * (RSTR * 2) + q * 16, ag + (size_t)row * K + q * 8);
        }
#pragma unroll
        for (int it = 0; it < 4; ++it) {
            int t = it * 256 + tid;
            int row = t >> 3, q = t & 7;
            cp16(sb + row * (RSTR * 2) + q * 16, bg + (size_t)row * K + q * 8);
        }
        asm volatile("cp.async.commit_group;");
    };

    load_tiles(0, 0);

    for (int c = 0; c < nc; ++c) {
        if (c + 1 < nc) {
            load_tiles(c + 1, (c + 1) & 1);
            asm volatile("cp.async.wait_group 1;");
        } else {
            asm volatile("cp.async.wait_group 0;");
        }
        __syncthreads();

        const int buf = c & 1;
        uint32_t aBase = smem_u32(smem + buf * STAGE_B);
        uint32_t bBase = aBase + OP_B;
        const int mat = lane >> 3, r8 = lane & 7;

#pragma unroll
        for (int ks = 0; ks < 4; ++ks) {
            uint32_t a[2][4];
#pragma unroll
            for (int f = 0; f < 2; ++f) {
                int row = warpM * 32 + f * 16 + (mat & 1) * 8 + r8;
                int kh  = mat >> 1;
                ldsm_x4(aBase + row * (RSTR * 2) + ks * 32 + kh * 16,
                        a[f][0], a[f][1], a[f][2], a[f][3]);
            }
            uint32_t b[8][2];
#pragma unroll
            for (int p = 0; p < 4; ++p) {
                int row = warpN * 64 + p * 16 + (mat >> 1) * 8 + r8;
                int kh  = mat & 1;
                uint32_t r0, r1, r2, r3;
                ldsm_x4(bBase + row * (RSTR * 2) + ks * 32 + kh * 16, r0, r1, r2, r3);
                b[2 * p][0] = r0; b[2 * p][1] = r1;
                b[2 * p + 1][0] = r2; b[2 * p + 1][1] = r3;
            }
#pragma unroll
            for (int f = 0; f < 2; ++f)
#pragma unroll
                for (int n = 0; n < 8; ++n)
                    mma16816(acc[f][n], a[f], b[n]);
        }
        __syncthreads();
    }

#pragma unroll
    for (int f = 0; f < 2; ++f) {
        int m0 = bm + warpM * 32 + f * 16 + (lane >> 2);
#pragma unroll
        for (int n = 0; n < 8; ++n) {
            int col = bn + warpN * 64 + n * 8 + 2 * (lane & 3);
            __half2 v0 = __floats2half2_rn(gelu_exact(acc[f][n][0]), gelu_exact(acc[f][n][1]));
            __half2 v1 = __floats2half2_rn(gelu_exact(acc[f][n][2]), gelu_exact(acc[f][n][3]));
            *(__half2*)(C + (size_t)m0 * N + col)       = v0;
            *(__half2*)(C + (size_t)(m0 + 8) * N + col) = v1;
        }
    }
}

// ---------------- fused layers 2+3: h1 -> h2(smem) -> z -> decision + flag ----------------
#define OPA23 (128 * RSTR * 2)                     // 18432
#define OPB23 (256 * RSTR * 2)                     // 36864
#define STAGE23 (OPA23 + OPB23)                    // 55296
#define HS_STRIDE 264                              // halfs per row (528 B)
#define HS_BYTES (128 * HS_STRIDE * 2)             // 67584
#define F23_SMEM (3 * STAGE23 + 4 * 128 * 4)       // 167936

__global__ __launch_bounds__(512, 1)
void fused23(const __half* __restrict__ A,         // h1 [M,512]
             const __half* __restrict__ Bw1,       // w1 [256,512]
             const __half* __restrict__ Bw2,       // w2 [128,256]
             const float* __restrict__ w3, const float* __restrict__ prev_m) {
    extern __shared__ __align__(16) char smem[];

    const int tid  = threadIdx.x;
    const int lane = tid & 31;
    const int wid  = tid >> 5;
    const int warpM = wid & 3;
    const int warpN = wid >> 2;
    const int bm = blockIdx.x * 128;
    const int K = H1DIM;

    float acc[2][8][4];
#pragma unroll
    for (int f = 0; f < 2; ++f)
#pragma unroll
        for (int n = 0; n < 8; ++n)
#pragma unroll
            for (int q = 0; q < 4; ++q) acc[f][n][q] = 0.0f;

    const int nc = K / BK;            // 8

    auto load_tiles = [&](int c, int buf) {
        const __half* ag = A + (size_t)bm * K + c * BK;
        const __half* bg = Bw1 + c * BK;
        uint32_t sa = smem_u32(smem + buf * STAGE23);
        uint32_t sb = sa + OPA23;
#pragma unroll
        for (int it = 0; it < 2; ++it) {
            int t = it * 512 + tid;
            int row = t >> 3, q = t & 7;
            cp16(sa + row * (RSTR * 2) + q * 16, ag + (size_t)row * K + q * 8);
        }
#pragma unroll
        for (int it = 0; it < 4; ++it) {
            int t = it * 512 + tid;
            int row = t >> 3, q = t & 7;
            cp16(sb + row * (RSTR * 2) + q * 16, bg + (size_t)row * K + q * 8);
        }
        asm volatile("cp.async.commit_group;");
    };

    load_tiles(0, 0);
    load_tiles(1, 1);

    for (int c = 0; c < nc; ++c) {
        if (c + 1 < nc) {
            asm volatile("cp.async.wait_group 1;");
        } else {
            asm volatile("cp.async.wait_group 0;");
        }
        __syncthreads();
        if (c + 2 < nc) load_tiles(c + 2, (c + 2) % 3);

        const int buf = c % 3;
        uint32_t aBase = smem_u32(smem + buf * STAGE23);
        uint32_t bBase = aBase + OPA23;
        const int mat = lane >> 3, r8 = lane & 7;

#pragma unroll
        for (int ks = 0; ks < 4; ++ks) {
            uint32_t a[2][4];
#pragma unroll
            for (int f = 0; f < 2; ++f) {
                int row = warpM * 32 + f * 16 + (mat & 1) * 8 + r8;
                int kh  = mat >> 1;
                ldsm_x4(aBase + row * (RSTR * 2) + ks * 32 + kh * 16,
                        a[f][0], a[f][1], a[f][2], a[f][3]);
            }
            uint32_t b[8][2];
#pragma unroll
            for (int p = 0; p < 4; ++p) {
                int row = warpN * 64 + p * 16 + (mat >> 1) * 8 + r8;
                int kh  = mat & 1;
                uint32_t r0, r1, r2, r3;
                ldsm_x4(bBase + row * (RSTR * 2) + ks * 32 + kh * 16, r0, r1, r2, r3);
                b[2 * p][0] = r0; b[2 * p][1] = r1;
                b[2 * p + 1][0] = r2; b[2 * p + 1][1] = r3;
            }
#pragma unroll
            for (int f = 0; f < 2; ++f)
#pragma unroll
                for (int n = 0; n < 8; ++n)
                    mma16816(acc[f][n], a[f], b[n]);
        }
    }
    __syncthreads();

    // ---- handoff: h2 = gelu(acc) -> smem (fp16); w2 -> smem via cp.async ----
    __half* hs = (__half*)smem;
    uint32_t w2s = smem_u32(smem + HS_BYTES);
#pragma unroll
    for (int it = 0; it < 8; ++it) {
        int t = it * 512 + tid;
        int row = t >> 5, q = t & 31;
        cp16(w2s + row * (HS_STRIDE * 2) + q * 16, Bw2 + (size_t)row * H2DIM + q * 8);
    }
    asm volatile("cp.async.commit_group;");

#pragma unroll
    for (int f = 0; f < 2; ++f) {
        int m0 = warpM * 32 + f * 16 + (lane >> 2);
#pragma unroll
        for (int n = 0; n < 8; ++n) {
            int col = warpN * 64 + n * 8 + 2 * (lane & 3);
            __half2 v0 = __floats2half2_rn(gelu_exact(acc[f][n][0]), gelu_exact(acc[f][n][1]));
            __half2 v1 = __floats2half2_rn(gelu_exact(acc[f][n][2]), gelu_exact(acc[f][n][3]));
            *(__half2*)(hs + (size_t)m0 * HS_STRIDE + col)       = v0;
            *(__half2*)(hs + (size_t)(m0 + 8) * HS_STRIDE + col) = v1;
        }
    }
    asm volatile("cp.async.wait_group 0;");
    __syncthreads();

    // ---- phase 2: y3[128,128] = h2[128,256] * w2[128,256]^T ----
    float acc2[2][4][4];
#pragma unroll
    for (int f = 0; f < 2; ++f)
#pragma unroll
        for (int n = 0; n < 4; ++n)
#pragma unroll
            for (int q = 0; q < 4; ++q) acc2[f][n][q] = 0.0f;

    {
        uint32_t aBase = smem_u32(hs);
        uint32_t bBase = w2s;
        const int mat = lane >> 3, r8 = lane & 7;
#pragma unroll
        for (int k16 = 0; k16 < 16; ++k16) {
            uint32_t a[2][4];
#pragma unroll
            for (int f = 0; f < 2; ++f) {
                int row = warpM * 32 + f * 16 + (mat & 1) * 8 + r8;
                int kh  = mat >> 1;
                ldsm_x4(aBase + row * (HS_STRIDE * 2) + k16 * 32 + kh * 16,
                        a[f][0], a[f][1], a[f][2], a[f][3]);
            }
            uint32_t b[4][2];
#pragma unroll
            for (int p = 0; p < 2; ++p) {
                int row = warpN * 32 + p * 16 + (mat >> 1) * 8 + r8;
                int kh  = mat & 1;
                uint32_t r0, r1, r2, r3;
                ldsm_x4(bBase + row * (HS_STRIDE * 2) + k16 * 32 + kh * 16, r0, r1, r2, r3);
                b[2 * p][0] = r0; b[2 * p][1] = r1;
                b[2 * p + 1][0] = r2; b[2 * p + 1][1] = r3;
            }
#pragma unroll
            for (int f = 0; f < 2; ++f)
#pragma unroll
                for (int n = 0; n < 4; ++n)
                    mma16816(acc2[f][n], a[f], b[n]);
        }
    }

    // ---- logit epilogue ----
    float* zsm = (float*)(smem + 3 * STAGE23);
    float zp[2][2];
    zp[0][0] = zp[0][1] = zp[1][0] = zp[1][1] = 0.0f;
#pragma unroll
    for (int f = 0; f < 2; ++f) {
#pragma unroll
        for (int n = 0; n < 4; ++n) {
            int col = warpN * 32 + n * 8 + 2 * (lane & 3);
            float w0 = __ldg(w3 + col), w1v = __ldg(w3 + col + 1);
            zp[f][0] += gelu_exact(acc2[f][n][0]) * w0 + gelu_exact(acc2[f][n][1]) * w1v;
            zp[f][1] += gelu_exact(acc2[f][n][2]) * w0 + gelu_exact(acc2[f][n][3]) * w1v;
        }
    }
#pragma unroll
    for (int f = 0; f < 2; ++f)
#pragma unroll
        for (int h = 0; h < 2; ++h) {
            float s = zp[f][h];
            s += __shfl_xor_sync(0xFFFFFFFFu, s, 1);
            s += __shfl_xor_sync(0xFFFFFFFFu, s, 2);
            zp[f][h] = s;
        }
    if ((lane & 3) == 0) {
#pragma unroll
        for (int f = 0; f < 2; ++f)
#pragma unroll
            for (int h = 0; h < 2; ++h)
                zsm[warpN * 128 + warpM * 32 + f * 16 + (lane >> 2) + 8 * h] = zp[f][h];
    }
    __syncthreads();
    if (tid < 128) {
        float s = zsm[tid] + zsm[128 + tid] + zsm[256 + tid] + zsm[384 + tid];
        int row = bm + tid;
        float pm = prev_m[row];
        float prob = 1.0f / (1.0f + expf(-s));
        float cm_raw = prob * pm;
        bool hard = cm_raw > 0.5f;
        g_cm[row] = hard ? 1.0f : 1e-10f;
        g_mk[row] = hard ? 1.0f : 0.0f;
        float thr = 5e-4f * fmaxf(1.0f, fabsf(pm));
        bool amb = fabsf(cm_raw - 0.5f) < thr;
        g_flag[row] = amb ? 1 : 0;
        if (amb) {
            int idx = atomicAdd(&g_count, 1);
            g_list[idx] = row;
        }
    }
}

// ---------------- combined: recompute blocks + finalize blocks, one launch ----------------
#define RG 16
#define NRB 128
#define RC_SMEM (RG * 512 * 2 * 4 + RG * 4)   // xs+h1s + cmv = 65600 B

__global__ __launch_bounds__(256)
void final_combined(const float* __restrict__ x, const float* __restrict__ W_L,
                    const float* __restrict__ W_l1, const float* __restrict__ W_l2,
                    const float* __restrict__ w3, const float* __restrict__ prev_m,
                    float* __restrict__ out, float* __restrict__ mask_out,
                    float* __restrict__ cm_out) {
    extern __shared__ float sm[];
    const int tid = threadIdx.x;

    if (blockIdx.x >= NRB) {
        // ---------- finalize role: 8 rows per block, skip flagged rows ----------
        const int warp = tid >> 5;
        const int lane = tid & 31;
        const size_t row = (size_t)(blockIdx.x - NRB) * 8 + warp;
        if (g_flag[row]) return;   // recompute block owns this row's outputs

        float cm = g_cm[row];
        if (lane == 0) {
            mask_out[row] = g_mk[row];
            cm_out[row]   = cm;
        }
        const float4* xin = (const float4*)(x + row * DDIM);
        float4*       xo  = (float4*)(out + row * DDIM);
#pragma unroll
        for (int i = 0; i < 4; ++i) {
            float4 v = xin[lane + 32 * i];
            v.x *= cm; v.y *= cm; v.z *= cm; v.w *= cm;
            __stcs(xo + lane + 32 * i, v);
        }
        return;
    }

    // ---------- recompute role (round-12 proven internals) ----------
    float* xs  = sm;            // [RG][512]
    float* h1s = sm + RG * 512; // [RG][512]
    float* h2s = sm;            // [RG][256] overwrites xs after layer1
    float* h3s = sm + RG * 256; // [RG][128]
    float* cmv = sm + RG * 512 * 2;  // [RG] exact cm per row

    const int count = g_count;

    for (int base = blockIdx.x * RG; base < count; base += NRB * RG) {
        const int nr = min(RG, count - base);

        for (int e = tid; e < RG * 512; e += 256) {
            int r = e >> 9, k = e & 511;
            xs[e] = (r < nr) ? x[(size_t)g_list[base + r] * DDIM + k] : 0.0f;
        }
        __syncthreads();

#pragma unroll 1
        for (int jj = 0; jj < 2; ++jj) {
            int j = tid + jj * 256;
            float a[RG];
#pragma unroll
            for (int r = 0; r < RG; ++r) a[r] = 0.0f;
            const float4* wr = (const float4*)(W_L + (size_t)j * DDIM);
            for (int k4 = 0; k4 < 128; ++k4) {
                float4 w = wr[k4];
#pragma unroll
                for (int r = 0; r < RG; ++r) {
                    const float* xr = xs + r * 512 + k4 * 4;
                    a[r] = fmaf(xr[0], w.x, a[r]);
                    a[r] = fmaf(xr[1], w.y, a[r]);
                    a[r] = fmaf(xr[2], w.z, a[r]);
                    a[r] = fmaf(xr[3], w.w, a[r]);
                }
            }
#pragma unroll
            for (int r = 0; r < RG; ++r) h1s[r * 512 + j] = gelu_exact(a[r]);
        }
        __syncthreads();

        {
            int j = tid;
            float a[RG];
#pragma unroll
            for (int r = 0; r < RG; ++r) a[r] = 0.0f;
            const float4* wr = (const float4*)(W_l1 + (size_t)j * H1DIM);
            for (int k4 = 0; k4 < 128; ++k4) {
                float4 w = wr[k4];
#pragma unroll
                for (int r = 0; r < RG; ++r) {
                    const float* hr = h1s + r * 512 + k4 * 4;
                    a[r] = fmaf(hr[0], w.x, a[r]);
                    a[r] = fmaf(hr[1], w.y, a[r]);
                    a[r] = fmaf(hr[2], w.z, a[r]);
                    a[r] = fmaf(hr[3], w.w, a[r]);
                }
            }
            __syncthreads();
#pragma unroll
            for (int r = 0; r < RG; ++r) h2s[r * 256 + j] = gelu_exact(a[r]);
        }
        __syncthreads();

        if (tid < 128) {
            int j = tid;
            float a[RG];
#pragma unroll
            for (int r = 0; r < RG; ++r) a[r] = 0.0f;
            const float4* wr = (const float4*)(W_l2 + (size_t)j * H2DIM);
            for (int k4 = 0; k4 < 64; ++k4) {
                float4 w = wr[k4];
#pragma unroll
                for (int r = 0; r < RG; ++r) {
                    const float* hr = h2s + r * 256 + k4 * 4;
                    a[r] = fmaf(hr[0], w.x, a[r]);
                    a[r] = fmaf(hr[1], w.y, a[r]);
                    a[r] = fmaf(hr[2], w.z, a[r]);
                    a[r] = fmaf(hr[3], w.w, a[r]);
                }
            }
#pragma unroll
            for (int r = 0; r < RG; ++r) h3s[r * 128 + j] = gelu_exact(a[r]);
        }
        __syncthreads();

        {
            const int warp = tid >> 5, lane = tid & 31;
#pragma unroll
            for (int h = 0; h < 2; ++h) {
                int r = warp + h * 8;
                float4 a4 = ((const float4*)(h3s + r * 128))[lane];
                float4 w4 = ((const float4*)w3)[lane];
                float s = a4.x * w4.x + a4.y * w4.y + a4.z * w4.z + a4.w * w4.w;
#pragma unroll
                for (int off = 16; off > 0; off >>= 1)
                    s += __shfl_xor_sync(0xFFFFFFFFu, s, off);
                if (lane == 0 && r < nr) {
                    int row = g_list[base + r];
                    float pm = prev_m[row];
                    float prob = 1.0f / (1.0f + expf(-s));
                    bool hard = prob * pm > 0.5f;
                    float cm = hard ? 1.0f : 1e-10f;
                    cmv[r] = cm;
                    mask_out[row] = hard ? 1.0f : 0.0f;
                    cm_out[row]   = cm;
                }
            }
        }
        __syncthreads();

        // write output rows for the flagged rows handled here
        for (int r = 0; r < nr; ++r) {
            int row = g_list[base + r];
            float cm = cmv[r];
            const float4* xin = (const float4*)(x + (size_t)row * DDIM);
            float4*       xo  = (float4*)(out + (size_t)row * DDIM);
            // 128 float4 per row, 256 threads -> first 128 threads write
            if (tid < 128) {
                float4 v = xin[tid];
                v.x *= cm; v.y *= cm; v.z *= cm; v.w *= cm;
                __stcs(xo + tid, v);
            }
        }
        __syncthreads();
    }
}

// ---------------- launch ----------------
extern "C" void kernel_launch(void* const* d_in, const int* in_sizes, int n_in,
                              void* d_out, int out_size) {
    const float* input  = (const float*)d_in[0];
    const float* prev_m = (const float*)d_in[2];
    const float* W_L    = (const float*)d_in[3];
    const float* W_l1   = (const float*)d_in[4];
    const float* W_l2   = (const float*)d_in[5];
    const float* W_l3   = (const float*)d_in[6];

    float* out      = (float*)d_out;
    float* mask_out = out + (size_t)MROWS * DDIM;
    float* cm_out   = mask_out + MROWS;

    __half *ia, *h1, *wL, *w1, *w2;
    cudaGetSymbolAddress((void**)&ia, g_ia);
    cudaGetSymbolAddress((void**)&h1, g_h1);
    cudaGetSymbolAddress((void**)&wL, g_wL);
    cudaGetSymbolAddress((void**)&w1, g_w1);
    cudaGetSymbolAddress((void**)&w2, g_w2);

    cudaFuncSetAttribute(hgemm_l1, cudaFuncAttributeMaxDynamicSharedMemorySize, GEMM_SMEM);
    cudaFuncSetAttribute(fused23,  cudaFuncAttributeMaxDynamicSharedMemorySize, F23_SMEM);
    cudaFuncSetAttribute(final_combined, cudaFuncAttributeMaxDynamicSharedMemorySize, RC_SMEM);

    // 1: all conversions + counter reset (single launch)
    {
        int ntot = MROWS * DDIM / 4 + (H1DIM * DDIM + H2DIM * H1DIM + H3DIM * H2DIM) / 4;
        conv_kernel<<<(ntot + 255) / 256, 256>>>(input, W_L, W_l1, W_l2);
    }

    // 2: layer 1 GEMM
    hgemm_l1<<<dim3(H1DIM / 128, MROWS / 128), 256, GEMM_SMEM>>>(ia, wL, h1, DDIM, H1DIM);

    // 3: fused layers 2+3 + logit + decision + flag
    fused23<<<MROWS / 128, 512, F23_SMEM>>>(h1, w1, w2, W_l3, prev_m);

    // 4: combined recompute (blocks 0..127) + finalize (blocks 128..8319)
    final_combined<<<NRB + MROWS / 8, 256, RC_SMEM>>>(
        input, W_L, W_l1, W_l2, W_l3, prev_m, out, mask_out, cm_out);
}

// round 15
// speedup vs baseline: 1.4881x; 1.0061x over previous
#include <cuda_runtime.h>
#include <cuda_fp16.h>
#include <math.h>
#include <stdint.h>

// Problem dims (fixed)
#define BDIM   128
#define NDIM   512
#define DDIM   512
#define MROWS  (BDIM*NDIM)          // 65536
#define H1DIM  512
#define H2DIM  256
#define H3DIM  128

// ---------------- static scratch ----------------
__device__ __half g_ia[(size_t)MROWS * DDIM];
__device__ __half g_h1[(size_t)MROWS * H1DIM];
__device__ __half g_wL[H1DIM * DDIM];
__device__ __half g_w1[H2DIM * H1DIM];
__device__ __half g_w2[H3DIM * H2DIM];
__device__ float  g_cm[MROWS];
__device__ float  g_mk[MROWS];
__device__ unsigned char g_flag[MROWS];
__device__ int    g_count;
__device__ int    g_list[MROWS];

// ---------------- helpers ----------------
__device__ __forceinline__ float gelu_exact(float x) {
    return 0.5f * x * (1.0f + erff(x * 0.70710678118654752f));
}
__device__ __forceinline__ uint32_t smem_u32(const void* p) {
    uint32_t a;
    asm("{ .reg .u64 t; cvta.to.shared.u64 t, %1; cvt.u32.u64 %0, t; }" : "=r"(a) : "l"(p));
    return a;
}
__device__ __forceinline__ void cp16(uint32_t s, const void* g) {
    asm volatile("cp.async.cg.shared.global [%0], [%1], 16;" :: "r"(s), "l"(g));
}
__device__ __forceinline__ void ldsm_x4(uint32_t addr, uint32_t& r0, uint32_t& r1,
                                        uint32_t& r2, uint32_t& r3) {
    asm volatile("ldmatrix.sync.aligned.m8n8.x4.shared.b16 {%0,%1,%2,%3}, [%4];"
                 : "=r"(r0), "=r"(r1), "=r"(r2), "=r"(r3) : "r"(addr));
}
__device__ __forceinline__ void mma16816(float* c, const uint32_t* a, const uint32_t* b) {
    asm volatile("mma.sync.aligned.m16n8k16.row.col.f32.f16.f16.f32 "
                 "{%0,%1,%2,%3}, {%4,%5,%6,%7}, {%8,%9}, {%0,%1,%2,%3};"
                 : "+f"(c[0]), "+f"(c[1]), "+f"(c[2]), "+f"(c[3])
                 : "r"(a[0]), "r"(a[1]), "r"(a[2]), "r"(a[3]), "r"(b[0]), "r"(b[1]));
}

// ---------------- conv: input f2h + 3 weight f2h + counter reset, ONE launch ----------------
__global__ void conv_kernel(const float* __restrict__ x,
                            const float* __restrict__ wL, const float* __restrict__ w1,
                            const float* __restrict__ w2) {
    const int nIn = MROWS * DDIM / 4;
    const int n1 = H1DIM * DDIM / 4, n2 = H2DIM * H1DIM / 4, n3 = H3DIM * H2DIM / 4;
    int i = blockIdx.x * blockDim.x + threadIdx.x;
    if (i == 0) g_count = 0;
    const float* src; __half* dst; int j;
    if (i < nIn)                      { src = x;  dst = g_ia; j = i; }
    else if ((j = i - nIn) < n1)      { src = wL; dst = g_wL; }
    else if ((j -= n1) < n2)          { src = w1; dst = g_w1; }
    else if ((j -= n2) < n3)          { src = w2; dst = g_w2; }
    else return;
    float4 v = ((const float4*)src)[j];
    ((__half2*)dst)[2 * j + 0] = __floats2half2_rn(v.x, v.y);
    ((__half2*)dst)[2 * j + 1] = __floats2half2_rn(v.z, v.w);
}

// ---------------- layer-1 GEMM (128x128 tile, BK=64, 2-stage, 2 CTA/SM) ----------------
#define BK 64
#define RSTR 72                                    // halfs per smem row (144 B)
#define OP_B    (128 * RSTR * 2)                   // 18432 B
#define STAGE_B (2 * OP_B)                         // 36864 B
#define GEMM_SMEM (2 * STAGE_B)                    // 73728 B

__global__ __launch_bounds__(256, 2)
void hgemm_l1(const __half* __restrict__ A, const __half* __restrict__ B,
              __half* __restrict__ C, int K, int N) {
    extern __shared__ __align__(16) char smem[];

    const int tid  = threadIdx.x;
    const int lane = tid & 31;
    const int wid  = tid >> 5;
    const int warpM = wid & 3;
    const int warpN = wid >> 2;
    const int bm = blockIdx.y * 128;
    const int bn = blockIdx.x * 128;

    float acc[2][8][4];
#pragma unroll
    for (int f = 0; f < 2; ++f)
#pragma unroll
        for (int n = 0; n < 8; ++n)
#pragma unroll
            for (int q = 0; q < 4; ++q) acc[f][n][q] = 0.0f;

    const int nc = K / BK;

    auto load_tiles = [&](int c, int buf) {
        const __half* ag = A + (size_t)bm * K + c * BK;
        const __half* bg = B + (size_t)bn * K + c * BK;
        uint32_t sa = smem_u32(smem + buf * STAGE_B);
        uint32_t sb = sa + OP_B;
#pragma unroll
        for (int it = 0; it < 4; ++it) {
            int t = it * 256 + tid;
            int row = t >> 3, q = t & 7;
            cp16(sa + row * (RSTR * 2) + q * 16, ag + (size_t)row * K + q * 8);
        }
#pragma unroll
        for (int it = 0; it < 4; ++it) {
            int t = it * 256 + tid;
            int row = t >> 3, q = t & 7;
            cp16(sb + row * (RSTR * 2) + q * 16, bg + (size_t)row * K + q * 8);
        }
        asm volatile("cp.async.commit_group;");
    };

    load_tiles(0, 0);

    for (int c = 0; c < nc; ++c) {
        if (c + 1 < nc) {
            load_tiles(c + 1, (c + 1) & 1);
            asm volatile("cp.async.wait_group 1;");
        } else {
            asm volatile("cp.async.wait_group 0;");
        }
        __syncthreads();

        const int buf = c & 1;
        uint32_t aBase = smem_u32(smem + buf * STAGE_B);
        uint32_t bBase = aBase + OP_B;
        const int mat = lane >> 3, r8 = lane & 7;

#pragma unroll
        for (int ks = 0; ks < 4; ++ks) {
            uint32_t a[2][4];
#pragma unroll
            for (int f = 0; f < 2; ++f) {
                int row = warpM * 32 + f * 16 + (mat & 1) * 8 + r8;
                int kh  = mat >> 1;
                ldsm_x4(aBase + row * (RSTR * 2) + ks * 32 + kh * 16,
                        a[f][0], a[f][1], a[f][2], a[f][3]);
            }
            uint32_t b[8][2];
#pragma unroll
            for (int p = 0; p < 4; ++p) {
                int row = warpN * 64 + p * 16 + (mat >> 1) * 8 + r8;
                int kh  = mat & 1;
                uint32_t r0, r1, r2, r3;
                ldsm_x4(bBase + row * (RSTR * 2) + ks * 32 + kh * 16, r0, r1, r2, r3);
                b[2 * p][0] = r0; b[2 * p][1] = r1;
                b[2 * p + 1][0] = r2; b[2 * p + 1][1] = r3;
            }
#pragma unroll
            for (int f = 0; f < 2; ++f)
#pragma unroll
                for (int n = 0; n < 8; ++n)
                    mma16816(acc[f][n], a[f], b[n]);
        }
        __syncthreads();
    }

#pragma unroll
    for (int f = 0; f < 2; ++f) {
        int m0 = bm + warpM * 32 + f * 16 + (lane >> 2);
#pragma unroll
        for (int n = 0; n < 8; ++n) {
            int col = bn + warpN * 64 + n * 8 + 2 * (lane & 3);
            __half2 v0 = __floats2half2_rn(gelu_exact(acc[f][n][0]), gelu_exact(acc[f][n][1]));
            __half2 v1 = __floats2half2_rn(gelu_exact(acc[f][n][2]), gelu_exact(acc[f][n][3]));
            *(__half2*)(C + (size_t)m0 * N + col)       = v0;
            *(__half2*)(C + (size_t)(m0 + 8) * N + col) = v1;
        }
    }
}

// ---------------- fused layers 2+3: h1 -> h2(smem) -> z -> decision + flag ----------------
#define OPA23 (128 * RSTR * 2)                     // 18432
#define OPB23 (256 * RSTR * 2)                     // 36864
#define STAGE23 (OPA23 + OPB23)                    // 55296
#define HS_STRIDE 264                              // halfs per row (528 B)
#define HS_BYTES (128 * HS_STRIDE * 2)             // 67584
#define F23_SMEM (3 * STAGE23 + 4 * 128 * 4)       // 167936

__global__ __launch_bounds__(512, 1)
void fused23(const __half* __restrict__ A,         // h1 [M,512]
             const __half* __restrict__ Bw1,       // w1 [256,512]
             const __half* __restrict__ Bw2,       // w2 [128,256]
             const float* __restrict__ w3, const float* __restrict__ prev_m) {
    extern __shared__ __align__(16) char smem[];

    const int tid  = threadIdx.x;
    const int lane = tid & 31;
    const int wid  = tid >> 5;
    const int warpM = wid & 3;
    const int warpN = wid >> 2;
    const int bm = blockIdx.x * 128;
    const int K = H1DIM;

    float acc[2][8][4];
#pragma unroll
    for (int f = 0; f < 2; ++f)
#pragma unroll
        for (int n = 0; n < 8; ++n)
#pragma unroll
            for (int q = 0; q < 4; ++q) acc[f][n][q] = 0.0f;

    const int nc = K / BK;            // 8

    auto load_tiles = [&](int c, int buf) {
        const __half* ag = A + (size_t)bm * K + c * BK;
        const __half* bg = Bw1 + c * BK;
        uint32_t sa = smem_u32(smem + buf * STAGE23);
        uint32_t sb = sa + OPA23;
#pragma unroll
        for (int it = 0; it < 2; ++it) {
            int t = it * 512 + tid;
            int row = t >> 3, q = t & 7;
            cp16(sa + row * (RSTR * 2) + q * 16, ag + (size_t)row * K + q * 8);
        }
#pragma unroll
        for (int it = 0; it < 4; ++it) {
            int t = it * 512 + tid;
            int row = t >> 3, q = t & 7;
            cp16(sb + row * (RSTR * 2) + q * 16, bg + (size_t)row * K + q * 8);
        }
        asm volatile("cp.async.commit_group;");
    };

    load_tiles(0, 0);
    load_tiles(1, 1);

    for (int c = 0; c < nc; ++c) {
        if (c + 1 < nc) {
            asm volatile("cp.async.wait_group 1;");
        } else {
            asm volatile("cp.async.wait_group 0;");
        }
        __syncthreads();
        if (c + 2 < nc) load_tiles(c + 2, (c + 2) % 3);

        const int buf = c % 3;
        uint32_t aBase = smem_u32(smem + buf * STAGE23);
        uint32_t bBase = aBase + OPA23;
        const int mat = lane >> 3, r8 = lane & 7;

#pragma unroll
        for (int ks = 0; ks < 4; ++ks) {
            uint32_t a[2][4];
#pragma unroll
            for (int f = 0; f < 2; ++f) {
                int row = warpM * 32 + f * 16 + (mat & 1) * 8 + r8;
                int kh  = mat >> 1;
                ldsm_x4(aBase + row * (RSTR * 2) + ks * 32 + kh * 16,
                        a[f][0], a[f][1], a[f][2], a[f][3]);
            }
            uint32_t b[8][2];
#pragma unroll
            for (int p = 0; p < 4; ++p) {
                int row = warpN * 64 + p * 16 + (mat >> 1) * 8 + r8;
                int kh  = mat & 1;
                uint32_t r0, r1, r2, r3;
                ldsm_x4(bBase + row * (RSTR * 2) + ks * 32 + kh * 16, r0, r1, r2, r3);
                b[2 * p][0] = r0; b[2 * p][1] = r1;
                b[2 * p + 1][0] = r2; b[2 * p + 1][1] = r3;
            }
#pragma unroll
            for (int f = 0; f < 2; ++f)
#pragma unroll
                for (int n = 0; n < 8; ++n)
                    mma16816(acc[f][n], a[f], b[n]);
        }
    }
    __syncthreads();

    // ---- handoff: h2 = gelu(acc) -> smem (fp16); w2 -> smem via cp.async ----
    __half* hs = (__half*)smem;
    uint32_t w2s = smem_u32(smem + HS_BYTES);
#pragma unroll
    for (int it = 0; it < 8; ++it) {
        int t = it * 512 + tid;
        int row = t >> 5, q = t & 31;
        cp16(w2s + row * (HS_STRIDE * 2) + q * 16, Bw2 + (size_t)row * H2DIM + q * 8);
    }
    asm volatile("cp.async.commit_group;");

#pragma unroll
    for (int f = 0; f < 2; ++f) {
        int m0 = warpM * 32 + f * 16 + (lane >> 2);
#pragma unroll
        for (int n = 0; n < 8; ++n) {
            int col = warpN * 64 + n * 8 + 2 * (lane & 3);
            __half2 v0 = __floats2half2_rn(gelu_exact(acc[f][n][0]), gelu_exact(acc[f][n][1]));
            __half2 v1 = __floats2half2_rn(gelu_exact(acc[f][n][2]), gelu_exact(acc[f][n][3]));
            *(__half2*)(hs + (size_t)m0 * HS_STRIDE + col)       = v0;
            *(__half2*)(hs + (size_t)(m0 + 8) * HS_STRIDE + col) = v1;
        }
    }
    asm volatile("cp.async.wait_group 0;");
    __syncthreads();

    // ---- phase 2: y3[128,128] = h2[128,256] * w2[128,256]^T ----
    float acc2[2][4][4];
#pragma unroll
    for (int f = 0; f < 2; ++f)
#pragma unroll
        for (int n = 0; n < 4; ++n)
#pragma unroll
            for (int q = 0; q < 4; ++q) acc2[f][n][q] = 0.0f;

    {
        uint32_t aBase = smem_u32(hs);
        uint32_t bBase = w2s;
        const int mat = lane >> 3, r8 = lane & 7;
#pragma unroll
        for (int k16 = 0; k16 < 16; ++k16) {
            uint32_t a[2][4];
#pragma unroll
            for (int f = 0; f < 2; ++f) {
                int row = warpM * 32 + f * 16 + (mat & 1) * 8 + r8;
                int kh  = mat >> 1;
                ldsm_x4(aBase + row * (HS_STRIDE * 2) + k16 * 32 + kh * 16,
                        a[f][0], a[f][1], a[f][2], a[f][3]);
            }
            uint32_t b[4][2];
#pragma unroll
            for (int p = 0; p < 2; ++p) {
                int row = warpN * 32 + p * 16 + (mat >> 1) * 8 + r8;
                int kh  = mat & 1;
                uint32_t r0, r1, r2, r3;
                ldsm_x4(bBase + row * (HS_STRIDE * 2) + k16 * 32 + kh * 16, r0, r1, r2, r3);
                b[2 * p][0] = r0; b[2 * p][1] = r1;
                b[2 * p + 1][0] = r2; b[2 * p + 1][1] = r3;
            }
#pragma unroll
            for (int f = 0; f < 2; ++f)
#pragma unroll
                for (int n = 0; n < 4; ++n)
                    mma16816(acc2[f][n], a[f], b[n]);
        }
    }

    // ---- logit epilogue ----
    float* zsm = (float*)(smem + 3 * STAGE23);
    float zp[2][2];
    zp[0][0] = zp[0][1] = zp[1][0] = zp[1][1] = 0.0f;
#pragma unroll
    for (int f = 0; f < 2; ++f) {
#pragma unroll
        for (int n = 0; n < 4; ++n) {
            int col = warpN * 32 + n * 8 + 2 * (lane & 3);
            float w0 = __ldg(w3 + col), w1v = __ldg(w3 + col + 1);
            zp[f][0] += gelu_exact(acc2[f][n][0]) * w0 + gelu_exact(acc2[f][n][1]) * w1v;
            zp[f][1] += gelu_exact(acc2[f][n][2]) * w0 + gelu_exact(acc2[f][n][3]) * w1v;
        }
    }
#pragma unroll
    for (int f = 0; f < 2; ++f)
#pragma unroll
        for (int h = 0; h < 2; ++h) {
            float s = zp[f][h];
            s += __shfl_xor_sync(0xFFFFFFFFu, s, 1);
            s += __shfl_xor_sync(0xFFFFFFFFu, s, 2);
            zp[f][h] = s;
        }
    if ((lane & 3) == 0) {
#pragma unroll
        for (int f = 0; f < 2; ++f)
#pragma unroll
            for (int h = 0; h < 2; ++h)
                zsm[warpN * 128 + warpM * 32 + f * 16 + (lane >> 2) + 8 * h] = zp[f][h];
    }
    __syncthreads();
    if (tid < 128) {
        float s = zsm[tid] + zsm[128 + tid] + zsm[256 + tid] + zsm[384 + tid];
        int row = bm + tid;
        float pm = prev_m[row];
        float prob = 1.0f / (1.0f + expf(-s));
        float cm_raw = prob * pm;
        bool hard = cm_raw > 0.5f;
        g_cm[row] = hard ? 1.0f : 1e-10f;
        g_mk[row] = hard ? 1.0f : 0.0f;
        float thr = 5e-4f * fmaxf(1.0f, fabsf(pm));
        bool amb = fabsf(cm_raw - 0.5f) < thr;
        g_flag[row] = amb ? 1 : 0;
        if (amb) {
            int idx = atomicAdd(&g_count, 1);
            g_list[idx] = row;
        }
    }
}

// ---------------- combined: recompute blocks + finalize blocks, one launch ----------------
#define RG 16
#define NRB 128
#define RC_SMEM (RG * 512 * 2 * 4 + RG * 4)   // xs+h1s + cmv = 65600 B

__global__ __launch_bounds__(256)
void final_combined(const float* __restrict__ x, const float* __restrict__ W_L,
                    const float* __restrict__ W_l1, const float* __restrict__ W_l2,
                    const float* __restrict__ w3, const float* __restrict__ prev_m,
                    float* __restrict__ out, float* __restrict__ mask_out,
                    float* __restrict__ cm_out) {
    extern __shared__ float sm[];
    const int tid = threadIdx.x;

    if (blockIdx.x >= NRB) {
        // ---------- finalize role: 8 rows per block, skip flagged rows ----------
        const int warp = tid >> 5;
        const int lane = tid & 31;
        const size_t row = (size_t)(blockIdx.x - NRB) * 8 + warp;
        if (g_flag[row]) return;   // recompute block owns this row's outputs

        float cm = g_cm[row];
        if (lane == 0) {
            mask_out[row] = g_mk[row];
            cm_out[row]   = cm;
        }
        const float4* xin = (const float4*)(x + row * DDIM);
        float4*       xo  = (float4*)(out + row * DDIM);
#pragma unroll
        for (int i = 0; i < 4; ++i) {
            float4 v = xin[lane + 32 * i];
            v.x *= cm; v.y *= cm; v.z *= cm; v.w *= cm;
            __stcs(xo + lane + 32 * i, v);
        }
        return;
    }

    // ---------- recompute role (round-12 internals + 2-deep weight pipeline) ----------
    float* xs  = sm;            // [RG][512]
    float* h1s = sm + RG * 512; // [RG][512]
    float* h2s = sm;            // [RG][256] overwrites xs after layer1
    float* h3s = sm + RG * 256; // [RG][128]
    float* cmv = sm + RG * 512 * 2;  // [RG] exact cm per row

    const int count = g_count;

    for (int base = blockIdx.x * RG; base < count; base += NRB * RG) {
        const int nr = min(RG, count - base);

        for (int e = tid; e < RG * 512; e += 256) {
            int r = e >> 9, k = e & 511;
            xs[e] = (r < nr) ? x[(size_t)g_list[base + r] * DDIM + k] : 0.0f;
        }
        __syncthreads();

        // ---- layer1: thread j and j+256; 2-deep weight prefetch ----
#pragma unroll 1
        for (int jj = 0; jj < 2; ++jj) {
            int j = tid + jj * 256;
            float a[RG];
#pragma unroll
            for (int r = 0; r < RG; ++r) a[r] = 0.0f;
            const float4* wr = (const float4*)(W_L + (size_t)j * DDIM);
            float4 w = wr[0];
#pragma unroll 1
            for (int k4 = 0; k4 < 128; ++k4) {
                float4 wn = wr[(k4 + 1) & 127];   // prefetch next (wraps harmlessly)
#pragma unroll
                for (int r = 0; r < RG; ++r) {
                    const float* xr = xs + r * 512 + k4 * 4;
                    a[r] = fmaf(xr[0], w.x, a[r]);
                    a[r] = fmaf(xr[1], w.y, a[r]);
                    a[r] = fmaf(xr[2], w.z, a[r]);
                    a[r] = fmaf(xr[3], w.w, a[r]);
                }
                w = wn;
            }
#pragma unroll
            for (int r = 0; r < RG; ++r) h1s[r * 512 + j] = gelu_exact(a[r]);
        }
        __syncthreads();

        // ---- layer2: thread j = tid; 2-deep weight prefetch ----
        {
            int j = tid;
            float a[RG];
#pragma unroll
            for (int r = 0; r < RG; ++r) a[r] = 0.0f;
            const float4* wr = (const float4*)(W_l1 + (size_t)j * H1DIM);
            float4 w = wr[0];
#pragma unroll 1
            for (int k4 = 0; k4 < 128; ++k4) {
                float4 wn = wr[(k4 + 1) & 127];
#pragma unroll
                for (int r = 0; r < RG; ++r) {
                    const float* hr = h1s + r * 512 + k4 * 4;
                    a[r] = fmaf(hr[0], w.x, a[r]);
                    a[r] = fmaf(hr[1], w.y, a[r]);
                    a[r] = fmaf(hr[2], w.z, a[r]);
                    a[r] = fmaf(hr[3], w.w, a[r]);
                }
                w = wn;
            }
            __syncthreads();
#pragma unroll
            for (int r = 0; r < RG; ++r) h2s[r * 256 + j] = gelu_exact(a[r]);
        }
        __syncthreads();

        // ---- layer3: threads 0..127; 2-deep weight prefetch ----
        if (tid < 128) {
            int j = tid;
            float a[RG];
#pragma unroll
            for (int r = 0; r < RG; ++r) a[r] = 0.0f;
            const float4* wr = (const float4*)(W_l2 + (size_t)j * H2DIM);
            float4 w = wr[0];
#pragma unroll 1
            for (int k4 = 0; k4 < 64; ++k4) {
                float4 wn = wr[(k4 + 1) & 63];
#pragma unroll
                for (int r = 0; r < RG; ++r) {
                    const float* hr = h2s + r * 256 + k4 * 4;
                    a[r] = fmaf(hr[0], w.x, a[r]);
                    a[r] = fmaf(hr[1], w.y, a[r]);
                    a[r] = fmaf(hr[2], w.z, a[r]);
                    a[r] = fmaf(hr[3], w.w, a[r]);
                }
                w = wn;
            }
#pragma unroll
            for (int r = 0; r < RG; ++r) h3s[r * 128 + j] = gelu_exact(a[r]);
        }
        __syncthreads();

        {
            const int warp = tid >> 5, lane = tid & 31;
#pragma unroll
            for (int h = 0; h < 2; ++h) {
                int r = warp + h * 8;
                float4 a4 = ((const float4*)(h3s + r * 128))[lane];
                float4 w4 = ((const float4*)w3)[lane];
                float s = a4.x * w4.x + a4.y * w4.y + a4.z * w4.z + a4.w * w4.w;
#pragma unroll
                for (int off = 16; off > 0; off >>= 1)
                    s += __shfl_xor_sync(0xFFFFFFFFu, s, off);
                if (lane == 0 && r < nr) {
                    int row = g_list[base + r];
                    float pm = prev_m[row];
                    float prob = 1.0f / (1.0f + expf(-s));
                    bool hard = prob * pm > 0.5f;
                    float cm = hard ? 1.0f : 1e-10f;
                    cmv[r] = cm;
                    mask_out[row] = hard ? 1.0f : 0.0f;
                    cm_out[row]   = cm;
                }
            }
        }
        __syncthreads();

        // write output rows for the flagged rows handled here
        for (int r = 0; r < nr; ++r) {
            int row = g_list[base + r];
            float cm = cmv[r];
            const float4* xin = (const float4*)(x + (size_t)row * DDIM);
            float4*       xo  = (float4*)(out + (size_t)row * DDIM);
            if (tid < 128) {
                float4 v = xin[tid];
                v.x *= cm; v.y *= cm; v.z *= cm; v.w *= cm;
                __stcs(xo + tid, v);
            }
        }
        __syncthreads();
    }
}

// ---------------- launch ----------------
extern "C" void kernel_launch(void* const* d_in, const int* in_sizes, int n_in,
                              void* d_out, int out_size) {
    const float* input  = (const float*)d_in[0];
    const float* prev_m = (const float*)d_in[2];
    const float* W_L    = (const float*)d_in[3];
    const float* W_l1   = (const float*)d_in[4];
    const float* W_l2   = (const float*)d_in[5];
    const float* W_l3   = (const float*)d_in[6];

    float* out      = (float*)d_out;
    float* mask_out = out + (size_t)MROWS * DDIM;
    float* cm_out   = mask_out + MROWS;

    __half *ia, *h1, *wL, *w1, *w2;
    cudaGetSymbolAddress((void**)&ia, g_ia);
    cudaGetSymbolAddress((void**)&h1, g_h1);
    cudaGetSymbolAddress((void**)&wL, g_wL);
    cudaGetSymbolAddress((void**)&w1, g_w1);
    cudaGetSymbolAddress((void**)&w2, g_w2);

    cudaFuncSetAttribute(hgemm_l1, cudaFuncAttributeMaxDynamicSharedMemorySize, GEMM_SMEM);
    cudaFuncSetAttribute(fused23,  cudaFuncAttributeMaxDynamicSharedMemorySize, F23_SMEM);
    cudaFuncSetAttribute(final_combined, cudaFuncAttributeMaxDynamicSharedMemorySize, RC_SMEM);

    // 1: all conversions + counter reset (single launch)
    {
        int ntot = MROWS * DDIM / 4 + (H1DIM * DDIM + H2DIM * H1DIM + H3DIM * H2DIM) / 4;
        conv_kernel<<<(ntot + 255) / 256, 256>>>(input, W_L, W_l1, W_l2);
    }

    // 2: layer 1 GEMM
    hgemm_l1<<<dim3(H1DIM / 128, MROWS / 128), 256, GEMM_SMEM>>>(ia, wL, h1, DDIM, H1DIM);

    // 3: fused layers 2+3 + logit + decision + flag
    fused23<<<MROWS / 128, 512, F23_SMEM>>>(h1, w1, w2, W_l3, prev_m);

    // 4: combined recompute (blocks 0..127, weight-pipelined) + finalize (blocks 128..8319)
    final_combined<<<NRB + MROWS / 8, 256, RC_SMEM>>>(
        input, W_L, W_l1, W_l2, W_l3, prev_m, out, mask_out, cm_out);
}

// round 16
// speedup vs baseline: 1.5746x; 1.0581x over previous
#include <cuda_runtime.h>
#include <cuda_fp16.h>
#include <math.h>
#include <stdint.h>

// Problem dims (fixed)
#define BDIM   128
#define NDIM   512
#define DDIM   512
#define MROWS  (BDIM*NDIM)          // 65536
#define H1DIM  512
#define H2DIM  256
#define H3DIM  128

// ---------------- static scratch ----------------
__device__ __half g_ia[(size_t)MROWS * DDIM];
__device__ __half g_h1[(size_t)MROWS * H1DIM];
__device__ __half g_wL[H1DIM * DDIM];
__device__ __half g_w1[H2DIM * H1DIM];
__device__ __half g_w2[H3DIM * H2DIM];
__device__ float  g_cm[MROWS];
__device__ float  g_mk[MROWS];
__device__ unsigned char g_flag[MROWS];
__device__ int    g_count;
__device__ int    g_list[MROWS];

// ---------------- helpers ----------------
__device__ __forceinline__ float gelu_exact(float x) {
    return 0.5f * x * (1.0f + erff(x * 0.70710678118654752f));
}
__device__ __forceinline__ uint32_t smem_u32(const void* p) {
    uint32_t a;
    asm("{ .reg .u64 t; cvta.to.shared.u64 t, %1; cvt.u32.u64 %0, t; }" : "=r"(a) : "l"(p));
    return a;
}
__device__ __forceinline__ void cp16(uint32_t s, const void* g) {
    asm volatile("cp.async.cg.shared.global [%0], [%1], 16;" :: "r"(s), "l"(g));
}
__device__ __forceinline__ void ldsm_x4(uint32_t addr, uint32_t& r0, uint32_t& r1,
                                        uint32_t& r2, uint32_t& r3) {
    asm volatile("ldmatrix.sync.aligned.m8n8.x4.shared.b16 {%0,%1,%2,%3}, [%4];"
                 : "=r"(r0), "=r"(r1), "=r"(r2), "=r"(r3) : "r"(addr));
}
__device__ __forceinline__ void mma16816(float* c, const uint32_t* a, const uint32_t* b) {
    asm volatile("mma.sync.aligned.m16n8k16.row.col.f32.f16.f16.f32 "
                 "{%0,%1,%2,%3}, {%4,%5,%6,%7}, {%8,%9}, {%0,%1,%2,%3};"
                 : "+f"(c[0]), "+f"(c[1]), "+f"(c[2]), "+f"(c[3])
                 : "r"(a[0]), "r"(a[1]), "r"(a[2]), "r"(a[3]), "r"(b[0]), "r"(b[1]));
}

// ---------------- conv: input f2h + 3 weight f2h + counter reset, ONE launch ----------------
__global__ void conv_kernel(const float* __restrict__ x,
                            const float* __restrict__ wL, const float* __restrict__ w1,
                            const float* __restrict__ w2) {
    const int nIn = MROWS * DDIM / 4;
    const int n1 = H1DIM * DDIM / 4, n2 = H2DIM * H1DIM / 4, n3 = H3DIM * H2DIM / 4;
    int i = blockIdx.x * blockDim.x + threadIdx.x;
    if (i == 0) g_count = 0;
    const float* src; __half* dst; int j;
    if (i < nIn)                      { src = x;  dst = g_ia; j = i; }
    else if ((j = i - nIn) < n1)      { src = wL; dst = g_wL; }
    else if ((j -= n1) < n2)          { src = w1; dst = g_w1; }
    else if ((j -= n2) < n3)          { src = w2; dst = g_w2; }
    else return;
    float4 v = ((const float4*)src)[j];
    ((__half2*)dst)[2 * j + 0] = __floats2half2_rn(v.x, v.y);
    ((__half2*)dst)[2 * j + 1] = __floats2half2_rn(v.z, v.w);
}

// ---------------- layer-1 GEMM (128x128 tile, BK=64, 2-stage, 2 CTA/SM) ----------------
#define BK 64
#define RSTR 72                                    // halfs per smem row (144 B)
#define OP_B    (128 * RSTR * 2)                   // 18432 B
#define STAGE_B (2 * OP_B)                         // 36864 B
#define GEMM_SMEM (2 * STAGE_B)                    // 73728 B

__global__ __launch_bounds__(256, 2)
void hgemm_l1(const __half* __restrict__ A, const __half* __restrict__ B,
              __half* __restrict__ C, int K, int N) {
    extern __shared__ __align__(16) char smem[];

    const int tid  = threadIdx.x;
    const int lane = tid & 31;
    const int wid  = tid >> 5;
    const int warpM = wid & 3;
    const int warpN = wid >> 2;
    const int bm = blockIdx.y * 128;
    const int bn = blockIdx.x * 128;

    float acc[2][8][4];
#pragma unroll
    for (int f = 0; f < 2; ++f)
#pragma unroll
        for (int n = 0; n < 8; ++n)
#pragma unroll
            for (int q = 0; q < 4; ++q) acc[f][n][q] = 0.0f;

    const int nc = K / BK;

    auto load_tiles = [&](int c, int buf) {
        const __half* ag = A + (size_t)bm * K + c * BK;
        const __half* bg = B + (size_t)bn * K + c * BK;
        uint32_t sa = smem_u32(smem + buf * STAGE_B);
        uint32_t sb = sa + OP_B;
#pragma unroll
        for (int it = 0; it < 4; ++it) {
            int t = it * 256 + tid;
            int row = t >> 3, q = t & 7;
            cp16(sa + row * (RSTR * 2) + q * 16, ag + (size_t)row * K + q * 8);
        }
#pragma unroll
        for (int it = 0; it < 4; ++it) {
            int t = it * 256 + tid;
            int row = t >> 3, q = t & 7;
            cp16(sb + row * (RSTR * 2) + q * 16, bg + (size_t)row * K + q * 8);
        }
        asm volatile("cp.async.commit_group;");
    };

    load_tiles(0, 0);

    for (int c = 0; c < nc; ++c) {
        if (c + 1 < nc) {
            load_tiles(c + 1, (c + 1) & 1);
            asm volatile("cp.async.wait_group 1;");
        } else {
            asm volatile("cp.async.wait_group 0;");
        }
        __syncthreads();

        const int buf = c & 1;
        uint32_t aBase = smem_u32(smem + buf * STAGE_B);
        uint32_t bBase = aBase + OP_B;
        const int mat = lane >> 3, r8 = lane & 7;

#pragma unroll
        for (int ks = 0; ks < 4; ++ks) {
            uint32_t a[2][4];
#pragma unroll
            for (int f = 0; f < 2; ++f) {
                int row = warpM * 32 + f * 16 + (mat & 1) * 8 + r8;
                int kh  = mat >> 1;
                ldsm_x4(aBase + row * (RSTR * 2) + ks * 32 + kh * 16,
                        a[f][0], a[f][1], a[f][2], a[f][3]);
            }
            uint32_t b[8][2];
#pragma unroll
            for (int p = 0; p < 4; ++p) {
                int row = warpN * 64 + p * 16 + (mat >> 1) * 8 + r8;
                int kh  = mat & 1;
                uint32_t r0, r1, r2, r3;
                ldsm_x4(bBase + row * (RSTR * 2) + ks * 32 + kh * 16, r0, r1, r2, r3);
                b[2 * p][0] = r0; b[2 * p][1] = r1;
                b[2 * p + 1][0] = r2; b[2 * p + 1][1] = r3;
            }
#pragma unroll
            for (int f = 0; f < 2; ++f)
#pragma unroll
                for (int n = 0; n < 8; ++n)
                    mma16816(acc[f][n], a[f], b[n]);
        }
        __syncthreads();
    }

#pragma unroll
    for (int f = 0; f < 2; ++f) {
        int m0 = bm + warpM * 32 + f * 16 + (lane >> 2);
#pragma unroll
        for (int n = 0; n < 8; ++n) {
            int col = bn + warpN * 64 + n * 8 + 2 * (lane & 3);
            __half2 v0 = __floats2half2_rn(gelu_exact(acc[f][n][0]), gelu_exact(acc[f][n][1]));
            __half2 v1 = __floats2half2_rn(gelu_exact(acc[f][n][2]), gelu_exact(acc[f][n][3]));
            *(__half2*)(C + (size_t)m0 * N + col)       = v0;
            *(__half2*)(C + (size_t)(m0 + 8) * N + col) = v1;
        }
    }
}

// ---------------- fused layers 2+3: h1 -> h2(smem) -> z -> decision + flag ----------------
#define OPA23 (128 * RSTR * 2)                     // 18432
#define OPB23 (256 * RSTR * 2)                     // 36864
#define STAGE23 (OPA23 + OPB23)                    // 55296
#define HS_STRIDE 264                              // halfs per row (528 B)
#define HS_BYTES (128 * HS_STRIDE * 2)             // 67584
#define F23_SMEM (3 * STAGE23 + 4 * 128 * 4)       // 167936

__global__ __launch_bounds__(512, 1)
void fused23(const __half* __restrict__ A,         // h1 [M,512]
             const __half* __restrict__ Bw1,       // w1 [256,512]
             const __half* __restrict__ Bw2,       // w2 [128,256]
             const float* __restrict__ w3, const float* __restrict__ prev_m) {
    extern __shared__ __align__(16) char smem[];

    const int tid  = threadIdx.x;
    const int lane = tid & 31;
    const int wid  = tid >> 5;
    const int warpM = wid & 3;
    const int warpN = wid >> 2;
    const int bm = blockIdx.x * 128;
    const int K = H1DIM;

    float acc[2][8][4];
#pragma unroll
    for (int f = 0; f < 2; ++f)
#pragma unroll
        for (int n = 0; n < 8; ++n)
#pragma unroll
            for (int q = 0; q < 4; ++q) acc[f][n][q] = 0.0f;

    const int nc = K / BK;            // 8

    auto load_tiles = [&](int c, int buf) {
        const __half* ag = A + (size_t)bm * K + c * BK;
        const __half* bg = Bw1 + c * BK;
        uint32_t sa = smem_u32(smem + buf * STAGE23);
        uint32_t sb = sa + OPA23;
#pragma unroll
        for (int it = 0; it < 2; ++it) {
            int t = it * 512 + tid;
            int row = t >> 3, q = t & 7;
            cp16(sa + row * (RSTR * 2) + q * 16, ag + (size_t)row * K + q * 8);
        }
#pragma unroll
        for (int it = 0; it < 4; ++it) {
            int t = it * 512 + tid;
            int row = t >> 3, q = t & 7;
            cp16(sb + row * (RSTR * 2) + q * 16, bg + (size_t)row * K + q * 8);
        }
        asm volatile("cp.async.commit_group;");
    };

    load_tiles(0, 0);
    load_tiles(1, 1);

    for (int c = 0; c < nc; ++c) {
        if (c + 1 < nc) {
            asm volatile("cp.async.wait_group 1;");
        } else {
            asm volatile("cp.async.wait_group 0;");
        }
        __syncthreads();
        if (c + 2 < nc) load_tiles(c + 2, (c + 2) % 3);

        const int buf = c % 3;
        uint32_t aBase = smem_u32(smem + buf * STAGE23);
        uint32_t bBase = aBase + OPA23;
        const int mat = lane >> 3, r8 = lane & 7;

#pragma unroll
        for (int ks = 0; ks < 4; ++ks) {
            uint32_t a[2][4];
#pragma unroll
            for (int f = 0; f < 2; ++f) {
                int row = warpM * 32 + f * 16 + (mat & 1) * 8 + r8;
                int kh  = mat >> 1;
                ldsm_x4(aBase + row * (RSTR * 2) + ks * 32 + kh * 16,
                        a[f][0], a[f][1], a[f][2], a[f][3]);
            }
            uint32_t b[8][2];
#pragma unroll
            for (int p = 0; p < 4; ++p) {
                int row = warpN * 64 + p * 16 + (mat >> 1) * 8 + r8;
                int kh  = mat & 1;
                uint32_t r0, r1, r2, r3;
                ldsm_x4(bBase + row * (RSTR * 2) + ks * 32 + kh * 16, r0, r1, r2, r3);
                b[2 * p][0] = r0; b[2 * p][1] = r1;
                b[2 * p + 1][0] = r2; b[2 * p + 1][1] = r3;
            }
#pragma unroll
            for (int f = 0; f < 2; ++f)
#pragma unroll
                for (int n = 0; n < 8; ++n)
                    mma16816(acc[f][n], a[f], b[n]);
        }
    }
    __syncthreads();

    // ---- handoff: h2 = gelu(acc) -> smem (fp16); w2 -> smem via cp.async ----
    __half* hs = (__half*)smem;
    uint32_t w2s = smem_u32(smem + HS_BYTES);
#pragma unroll
    for (int it = 0; it < 8; ++it) {
        int t = it * 512 + tid;
        int row = t >> 5, q = t & 31;
        cp16(w2s + row * (HS_STRIDE * 2) + q * 16, Bw2 + (size_t)row * H2DIM + q * 8);
    }
    asm volatile("cp.async.commit_group;");

#pragma unroll
    for (int f = 0; f < 2; ++f) {
        int m0 = warpM * 32 + f * 16 + (lane >> 2);
#pragma unroll
        for (int n = 0; n < 8; ++n) {
            int col = warpN * 64 + n * 8 + 2 * (lane & 3);
            __half2 v0 = __floats2half2_rn(gelu_exact(acc[f][n][0]), gelu_exact(acc[f][n][1]));
            __half2 v1 = __floats2half2_rn(gelu_exact(acc[f][n][2]), gelu_exact(acc[f][n][3]));
            *(__half2*)(hs + (size_t)m0 * HS_STRIDE + col)       = v0;
            *(__half2*)(hs + (size_t)(m0 + 8) * HS_STRIDE + col) = v1;
        }
    }
    asm volatile("cp.async.wait_group 0;");
    __syncthreads();

    // ---- phase 2: y3[128,128] = h2[128,256] * w2[128,256]^T ----
    float acc2[2][4][4];
#pragma unroll
    for (int f = 0; f < 2; ++f)
#pragma unroll
        for (int n = 0; n < 4; ++n)
#pragma unroll
            for (int q = 0; q < 4; ++q) acc2[f][n][q] = 0.0f;

    {
        uint32_t aBase = smem_u32(hs);
        uint32_t bBase = w2s;
        const int mat = lane >> 3, r8 = lane & 7;
#pragma unroll
        for (int k16 = 0; k16 < 16; ++k16) {
            uint32_t a[2][4];
#pragma unroll
            for (int f = 0; f < 2; ++f) {
                int row = warpM * 32 + f * 16 + (mat & 1) * 8 + r8;
                int kh  = mat >> 1;
                ldsm_x4(aBase + row * (HS_STRIDE * 2) + k16 * 32 + kh * 16,
                        a[f][0], a[f][1], a[f][2], a[f][3]);
            }
            uint32_t b[4][2];
#pragma unroll
            for (int p = 0; p < 2; ++p) {
                int row = warpN * 32 + p * 16 + (mat >> 1) * 8 + r8;
                int kh  = mat & 1;
                uint32_t r0, r1, r2, r3;
                ldsm_x4(bBase + row * (HS_STRIDE * 2) + k16 * 32 + kh * 16, r0, r1, r2, r3);
                b[2 * p][0] = r0; b[2 * p][1] = r1;
                b[2 * p + 1][0] = r2; b[2 * p + 1][1] = r3;
            }
#pragma unroll
            for (int f = 0; f < 2; ++f)
#pragma unroll
                for (int n = 0; n < 4; ++n)
                    mma16816(acc2[f][n], a[f], b[n]);
        }
    }

    // ---- logit epilogue ----
    float* zsm = (float*)(smem + 3 * STAGE23);
    float zp[2][2];
    zp[0][0] = zp[0][1] = zp[1][0] = zp[1][1] = 0.0f;
#pragma unroll
    for (int f = 0; f < 2; ++f) {
#pragma unroll
        for (int n = 0; n < 4; ++n) {
            int col = warpN * 32 + n * 8 + 2 * (lane & 3);
            float w0 = __ldg(w3 + col), w1v = __ldg(w3 + col + 1);
            zp[f][0] += gelu_exact(acc2[f][n][0]) * w0 + gelu_exact(acc2[f][n][1]) * w1v;
            zp[f][1] += gelu_exact(acc2[f][n][2]) * w0 + gelu_exact(acc2[f][n][3]) * w1v;
        }
    }
#pragma unroll
    for (int f = 0; f < 2; ++f)
#pragma unroll
        for (int h = 0; h < 2; ++h) {
            float s = zp[f][h];
            s += __shfl_xor_sync(0xFFFFFFFFu, s, 1);
            s += __shfl_xor_sync(0xFFFFFFFFu, s, 2);
            zp[f][h] = s;
        }
    if ((lane & 3) == 0) {
#pragma unroll
        for (int f = 0; f < 2; ++f)
#pragma unroll
            for (int h = 0; h < 2; ++h)
                zsm[warpN * 128 + warpM * 32 + f * 16 + (lane >> 2) + 8 * h] = zp[f][h];
    }
    __syncthreads();
    if (tid < 128) {
        float s = zsm[tid] + zsm[128 + tid] + zsm[256 + tid] + zsm[384 + tid];
        int row = bm + tid;
        float pm = prev_m[row];
        float prob = 1.0f / (1.0f + expf(-s));
        float cm_raw = prob * pm;
        bool hard = cm_raw > 0.5f;
        g_cm[row] = hard ? 1.0f : 1e-10f;
        g_mk[row] = hard ? 1.0f : 0.0f;
        float thr = 5e-4f * fmaxf(1.0f, fabsf(pm));
        bool amb = fabsf(cm_raw - 0.5f) < thr;
        g_flag[row] = amb ? 1 : 0;
        if (amb) {
            int idx = atomicAdd(&g_count, 1);
            g_list[idx] = row;
        }
    }
}

// ---------------- combined: recompute blocks + finalize blocks, one launch ----------------
#define RG 16
#define NRB 256
#define RC_SMEM (RG * 512 * 2 * 4 + RG * 4)   // xs+h1s + cmv = 65600 B

__global__ __launch_bounds__(256)
void final_combined(const float* __restrict__ x, const float* __restrict__ W_L,
                    const float* __restrict__ W_l1, const float* __restrict__ W_l2,
                    const float* __restrict__ w3, const float* __restrict__ prev_m,
                    float* __restrict__ out, float* __restrict__ mask_out,
                    float* __restrict__ cm_out) {
    extern __shared__ float sm[];
    const int tid = threadIdx.x;

    if (blockIdx.x >= NRB) {
        // ---------- finalize role: 8 rows per block, skip flagged rows ----------
        const int warp = tid >> 5;
        const int lane = tid & 31;
        const size_t row = (size_t)(blockIdx.x - NRB) * 8 + warp;
        if (g_flag[row]) return;   // recompute block owns this row's outputs

        float cm = g_cm[row];
        if (lane == 0) {
            mask_out[row] = g_mk[row];
            cm_out[row]   = cm;
        }
        const float4* xin = (const float4*)(x + row * DDIM);
        float4*       xo  = (float4*)(out + row * DDIM);
#pragma unroll
        for (int i = 0; i < 4; ++i) {
            float4 v = xin[lane + 32 * i];
            v.x *= cm; v.y *= cm; v.z *= cm; v.w *= cm;
            __stcs(xo + lane + 32 * i, v);
        }
        return;
    }

    // ---------- recompute role: round-12 internals + explicit 4-deep weight prefetch ----------
    float* xs  = sm;            // [RG][512]
    float* h1s = sm + RG * 512; // [RG][512]
    float* h2s = sm;            // [RG][256] overwrites xs after layer1
    float* h3s = sm + RG * 256; // [RG][128]
    float* cmv = sm + RG * 512 * 2;  // [RG] exact cm per row

    const int count = g_count;

    for (int base = blockIdx.x * RG; base < count; base += NRB * RG) {
        const int nr = min(RG, count - base);

        for (int e = tid; e < RG * 512; e += 256) {
            int r = e >> 9, k = e & 511;
            xs[e] = (r < nr) ? x[(size_t)g_list[base + r] * DDIM + k] : 0.0f;
        }
        __syncthreads();

        // ---- layer1: thread j and j+256; 4-deep weight prefetch ----
#pragma unroll 1
        for (int jj = 0; jj < 2; ++jj) {
            int j = tid + jj * 256;
            float a[RG];
#pragma unroll
            for (int r = 0; r < RG; ++r) a[r] = 0.0f;
            const float4* wr = (const float4*)(W_L + (size_t)j * DDIM);
#pragma unroll 1
            for (int k4 = 0; k4 < 128; k4 += 4) {
                float4 w0 = wr[k4 + 0];
                float4 w1 = wr[k4 + 1];
                float4 w2 = wr[k4 + 2];
                float4 w3v = wr[k4 + 3];
#pragma unroll
                for (int r = 0; r < RG; ++r) {
                    const float* xr = xs + r * 512 + k4 * 4;
                    float t = a[r];
                    t = fmaf(xr[0],  w0.x, t);  t = fmaf(xr[1],  w0.y, t);
                    t = fmaf(xr[2],  w0.z, t);  t = fmaf(xr[3],  w0.w, t);
                    t = fmaf(xr[4],  w1.x, t);  t = fmaf(xr[5],  w1.y, t);
                    t = fmaf(xr[6],  w1.z, t);  t = fmaf(xr[7],  w1.w, t);
                    t = fmaf(xr[8],  w2.x, t);  t = fmaf(xr[9],  w2.y, t);
                    t = fmaf(xr[10], w2.z, t);  t = fmaf(xr[11], w2.w, t);
                    t = fmaf(xr[12], w3v.x, t); t = fmaf(xr[13], w3v.y, t);
                    t = fmaf(xr[14], w3v.z, t); t = fmaf(xr[15], w3v.w, t);
                    a[r] = t;
                }
            }
#pragma unroll
            for (int r = 0; r < RG; ++r) h1s[r * 512 + j] = gelu_exact(a[r]);
        }
        __syncthreads();

        // ---- layer2: thread j = tid; 4-deep weight prefetch ----
        {
            int j = tid;
            float a[RG];
#pragma unroll
            for (int r = 0; r < RG; ++r) a[r] = 0.0f;
            const float4* wr = (const float4*)(W_l1 + (size_t)j * H1DIM);
#pragma unroll 1
            for (int k4 = 0; k4 < 128; k4 += 4) {
                float4 w0 = wr[k4 + 0];
                float4 w1 = wr[k4 + 1];
                float4 w2 = wr[k4 + 2];
                float4 w3v = wr[k4 + 3];
#pragma unroll
                for (int r = 0; r < RG; ++r) {
                    const float* hr = h1s + r * 512 + k4 * 4;
                    float t = a[r];
                    t = fmaf(hr[0],  w0.x, t);  t = fmaf(hr[1],  w0.y, t);
                    t = fmaf(hr[2],  w0.z, t);  t = fmaf(hr[3],  w0.w, t);
                    t = fmaf(hr[4],  w1.x, t);  t = fmaf(hr[5],  w1.y, t);
                    t = fmaf(hr[6],  w1.z, t);  t = fmaf(hr[7],  w1.w, t);
                    t = fmaf(hr[8],  w2.x, t);  t = fmaf(hr[9],  w2.y, t);
                    t = fmaf(hr[10], w2.z, t);  t = fmaf(hr[11], w2.w, t);
                    t = fmaf(hr[12], w3v.x, t); t = fmaf(hr[13], w3v.y, t);
                    t = fmaf(hr[14], w3v.z, t); t = fmaf(hr[15], w3v.w, t);
                    a[r] = t;
                }
            }
            __syncthreads();
#pragma unroll
            for (int r = 0; r < RG; ++r) h2s[r * 256 + j] = gelu_exact(a[r]);
        }
        __syncthreads();

        // ---- layer3: threads 0..127; 4-deep weight prefetch ----
        if (tid < 128) {
            int j = tid;
            float a[RG];
#pragma unroll
            for (int r = 0; r < RG; ++r) a[r] = 0.0f;
            const float4* wr = (const float4*)(W_l2 + (size_t)j * H2DIM);
#pragma unroll 1
            for (int k4 = 0; k4 < 64; k4 += 4) {
                float4 w0 = wr[k4 + 0];
                float4 w1 = wr[k4 + 1];
                float4 w2 = wr[k4 + 2];
                float4 w3v = wr[k4 + 3];
#pragma unroll
                for (int r = 0; r < RG; ++r) {
                    const float* hr = h2s + r * 256 + k4 * 4;
                    float t = a[r];
                    t = fmaf(hr[0],  w0.x, t);  t = fmaf(hr[1],  w0.y, t);
                    t = fmaf(hr[2],  w0.z, t);  t = fmaf(hr[3],  w0.w, t);
                    t = fmaf(hr[4],  w1.x, t);  t = fmaf(hr[5],  w1.y, t);
                    t = fmaf(hr[6],  w1.z, t);  t = fmaf(hr[7],  w1.w, t);
                    t = fmaf(hr[8],  w2.x, t);  t = fmaf(hr[9],  w2.y, t);
                    t = fmaf(hr[10], w2.z, t);  t = fmaf(hr[11], w2.w, t);
                    t = fmaf(hr[12], w3v.x, t); t = fmaf(hr[13], w3v.y, t);
                    t = fmaf(hr[14], w3v.z, t); t = fmaf(hr[15], w3v.w, t);
                    a[r] = t;
                }
            }
#pragma unroll
            for (int r = 0; r < RG; ++r) h3s[r * 128 + j] = gelu_exact(a[r]);
        }
        __syncthreads();

        {
            const int warp = tid >> 5, lane = tid & 31;
#pragma unroll
            for (int h = 0; h < 2; ++h) {
                int r = warp + h * 8;
                float4 a4 = ((const float4*)(h3s + r * 128))[lane];
                float4 w4 = ((const float4*)w3)[lane];
                float s = a4.x * w4.x + a4.y * w4.y + a4.z * w4.z + a4.w * w4.w;
#pragma unroll
                for (int off = 16; off > 0; off >>= 1)
                    s += __shfl_xor_sync(0xFFFFFFFFu, s, off);
                if (lane == 0 && r < nr) {
                    int row = g_list[base + r];
                    float pm = prev_m[row];
                    float prob = 1.0f / (1.0f + expf(-s));
                    bool hard = prob * pm > 0.5f;
                    float cm = hard ? 1.0f : 1e-10f;
                    cmv[r] = cm;
                    mask_out[row] = hard ? 1.0f : 0.0f;
                    cm_out[row]   = cm;
                }
            }
        }
        __syncthreads();

        // write output rows for the flagged rows handled here
        for (int r = 0; r < nr; ++r) {
            int row = g_list[base + r];
            float cm = cmv[r];
            const float4* xin = (const float4*)(x + (size_t)row * DDIM);
            float4*       xo  = (float4*)(out + (size_t)row * DDIM);
            if (tid < 128) {
                float4 v = xin[tid];
                v.x *= cm; v.y *= cm; v.z *= cm; v.w *= cm;
                __stcs(xo + tid, v);
            }
        }
        __syncthreads();
    }
}

// ---------------- launch ----------------
extern "C" void kernel_launch(void* const* d_in, const int* in_sizes, int n_in,
                              void* d_out, int out_size) {
    const float* input  = (const float*)d_in[0];
    const float* prev_m = (const float*)d_in[2];
    const float* W_L    = (const float*)d_in[3];
    const float* W_l1   = (const float*)d_in[4];
    const float* W_l2   = (const float*)d_in[5];
    const float* W_l3   = (const float*)d_in[6];

    float* out      = (float*)d_out;
    float* mask_out = out + (size_t)MROWS * DDIM;
    float* cm_out   = mask_out + MROWS;

    __half *ia, *h1, *wL, *w1, *w2;
    cudaGetSymbolAddress((void**)&ia, g_ia);
    cudaGetSymbolAddress((void**)&h1, g_h1);
    cudaGetSymbolAddress((void**)&wL, g_wL);
    cudaGetSymbolAddress((void**)&w1, g_w1);
    cudaGetSymbolAddress((void**)&w2, g_w2);

    cudaFuncSetAttribute(hgemm_l1, cudaFuncAttributeMaxDynamicSharedMemorySize, GEMM_SMEM);
    cudaFuncSetAttribute(fused23,  cudaFuncAttributeMaxDynamicSharedMemorySize, F23_SMEM);
    cudaFuncSetAttribute(final_combined, cudaFuncAttributeMaxDynamicSharedMemorySize, RC_SMEM);

    // 1: all conversions + counter reset (single launch)
    {
        int ntot = MROWS * DDIM / 4 + (H1DIM * DDIM + H2DIM * H1DIM + H3DIM * H2DIM) / 4;
        conv_kernel<<<(ntot + 255) / 256, 256>>>(input, W_L, W_l1, W_l2);
    }

    // 2: layer 1 GEMM
    hgemm_l1<<<dim3(H1DIM / 128, MROWS / 128), 256, GEMM_SMEM>>>(ia, wL, h1, DDIM, H1DIM);

    // 3: fused layers 2+3 + logit + decision + flag
    fused23<<<MROWS / 128, 512, F23_SMEM>>>(h1, w1, w2, W_l3, prev_m);

    // 4: combined recompute (blocks 0..255, 4-deep prefetch) + finalize (blocks 256..8447)
    final_combined<<<NRB + MROWS / 8, 256, RC_SMEM>>>(
        input, W_L, W_l1, W_l2, W_l3, prev_m, out, mask_out, cm_out);
}